// round 4
// baseline (speedup 1.0000x reference)
#include <cuda_runtime.h>
#include <stdint.h>

#define THREADS 256
#define TILE 128
#define NPER 50000

// shared floats: Z1(128*132) + Z2(128*132) + h1w/g1w(512*2) + 4 bias vecs(128*4)
//              + ow(384) + ob(4) + y0/y/k1/k2/k3 (384*5)
#define SMEM_FLOATS (128*132*2 + 512*2 + 128*4 + 384 + 4 + 384*5)

static __device__ __forceinline__ uint32_t f2tf32(float x) {
    uint32_t r;
    asm("cvt.rna.tf32.f32 %0, %1;" : "=r"(r) : "f"(x));
    return r;
}

static __device__ __forceinline__ void mma8(float d[4], const uint32_t a[4],
                                            uint32_t b0, uint32_t b1) {
    asm volatile(
        "mma.sync.aligned.m16n8k8.row.col.f32.tf32.tf32.f32 "
        "{%0,%1,%2,%3}, {%4,%5,%6,%7}, {%8,%9}, {%0,%1,%2,%3};\n"
        : "+f"(d[0]), "+f"(d[1]), "+f"(d[2]), "+f"(d[3])
        : "r"(a[0]), "r"(a[1]), "r"(a[2]), "r"(a[3]), "r"(b0), "r"(b1));
}

static __device__ __forceinline__ float fsig(float x) {
    return __fdividef(1.0f, 1.0f + __expf(-x));
}

struct Bufs {
    float *Z1, *Z2, *h1w, *g1w, *h1b, *g1b, *h2b, *g2b, *ow, *ob;
};

// One field evaluation for the block's 128 points: y (shared [3][128]) -> kdst (shared [3][128])
static __device__ __forceinline__ void field_eval(
    float t, const float* __restrict__ yb, float* __restrict__ kdst,
    const Bufs& B, const uint32_t (&Ah)[16][4], const uint32_t (&Ag)[16][4],
    int tid, int warp, int lane)
{
    // ---- layer 1 (4 -> 128, gated), write z1 as tf32 into Z1[ch][p] ----
    {
        const int p = tid & 127;
        const float zx = yb[p], zy = yb[128 + p], zz = yb[256 + p];
        for (int ch = (tid >> 7); ch < 128; ch += 2) {
            const float* wh = B.h1w + ch * 4;
            const float* wg = B.g1w + ch * 4;
            float h  = B.h1b[ch] + wh[0]*zx + wh[1]*zy + wh[2]*zz + wh[3]*t;
            float gg = B.g1b[ch] + wg[0]*zx + wg[1]*zy + wg[2]*zz + wg[3]*t;
            float z = fmaxf(h * fsig(gg), 0.0f);
            B.Z1[ch * 132 + p] = __uint_as_float(f2tf32(z));
        }
    }
    __syncthreads();

    // ---- layer 2: two 128x128x128 GEMMs (h2, g2) on the tensor pipe,
    //      gate-combine in registers, z2 fp32 -> Z2[ch][p] ----
    {
        const int g = lane >> 2, tg = lane & 3;
        const int row = warp * 16 + g;
        const float bh0 = B.h2b[row], bh1 = B.h2b[row + 8];
        const float bg0 = B.g2b[row], bg1 = B.g2b[row + 8];
        for (int n0 = 0; n0 < 128; n0 += 8) {
            float dh[4] = {0.f, 0.f, 0.f, 0.f};
            float dg[4] = {0.f, 0.f, 0.f, 0.f};
            #pragma unroll
            for (int kk = 0; kk < 16; ++kk) {
                uint32_t b0 = __float_as_uint(B.Z1[(kk*8     + tg) * 132 + n0 + g]);
                uint32_t b1 = __float_as_uint(B.Z1[(kk*8 + 4 + tg) * 132 + n0 + g]);
                mma8(dh, Ah[kk], b0, b1);
                mma8(dg, Ag[kk], b0, b1);
            }
            float z00 = fmaxf((dh[0] + bh0) * fsig(dg[0] + bg0), 0.f);
            float z01 = fmaxf((dh[1] + bh0) * fsig(dg[1] + bg0), 0.f);
            float z10 = fmaxf((dh[2] + bh1) * fsig(dg[2] + bg1), 0.f);
            float z11 = fmaxf((dh[3] + bh1) * fsig(dg[3] + bg1), 0.f);
            int col = n0 + 2 * tg;
            *(float2*)(B.Z2 + row       * 132 + col) = make_float2(z00, z01);
            *(float2*)(B.Z2 + (row + 8) * 132 + col) = make_float2(z10, z11);
        }
    }
    __syncthreads();

    // ---- out layer (128 -> 3) + tanh*0.5, 2 threads per point ----
    {
        const int q = tid & 1, p = tid >> 1;
        float d0 = 0.f, d1 = 0.f, d2 = 0.f;
        const int chb = q * 64;
        #pragma unroll 4
        for (int i = 0; i < 64; ++i) {
            int ch = chb + i;
            float z = B.Z2[ch * 132 + p];
            d0 = fmaf(B.ow[ch], z, d0);
            d1 = fmaf(B.ow[128 + ch], z, d1);
            d2 = fmaf(B.ow[256 + ch], z, d2);
        }
        d0 += __shfl_xor_sync(0xffffffffu, d0, 1);
        d1 += __shfl_xor_sync(0xffffffffu, d1, 1);
        d2 += __shfl_xor_sync(0xffffffffu, d2, 1);
        if (q == 0) {
            kdst[p]       = tanhf(d0 + B.ob[0]) * 0.5f;
            kdst[128 + p] = tanhf(d1 + B.ob[1]) * 0.5f;
            kdst[256 + p] = tanhf(d2 + B.ob[2]) * 0.5f;
        }
    }
    __syncthreads();
}

__global__ void __launch_bounds__(THREADS, 1)
node_kernel(const float* __restrict__ x0,
            const float* __restrict__ h1_w, const float* __restrict__ h1_b,
            const float* __restrict__ g1_w, const float* __restrict__ g1_b,
            const float* __restrict__ h2_w, const float* __restrict__ h2_b,
            const float* __restrict__ g2_w, const float* __restrict__ g2_b,
            const float* __restrict__ out_w, const float* __restrict__ out_b,
            float* __restrict__ yout, int P)
{
    extern __shared__ float sm[];
    Bufs B;
    B.Z1  = sm;
    B.Z2  = B.Z1 + 128 * 132;
    B.h1w = B.Z2 + 128 * 132;
    B.g1w = B.h1w + 512;
    B.h1b = B.g1w + 512;
    B.g1b = B.h1b + 128;
    B.h2b = B.g1b + 128;
    B.g2b = B.h2b + 128;
    B.ow  = B.g2b + 128;
    B.ob  = B.ow + 384;
    float* y0b = B.ob + 4;
    float* yb  = y0b + 384;
    float* k1b = yb  + 384;
    float* k2b = k1b + 384;
    float* k3b = k2b + 384;

    const int tid  = threadIdx.x;
    const int warp = tid >> 5;
    const int lane = tid & 31;

    // stage small weights into shared
    for (int i = tid; i < 512; i += THREADS) { B.h1w[i] = h1_w[i]; B.g1w[i] = g1_w[i]; }
    for (int i = tid; i < 128; i += THREADS) {
        B.h1b[i] = h1_b[i]; B.g1b[i] = g1_b[i];
        B.h2b[i] = h2_b[i]; B.g2b[i] = g2_b[i];
    }
    for (int i = tid; i < 384; i += THREADS) B.ow[i] = out_w[i];
    if (tid < 3) B.ob[tid] = out_b[tid];

    // A fragments (tf32) for h2 and g2, K=128 -> 16 k-steps, warp owns rows [warp*16, warp*16+16)
    uint32_t Ah[16][4], Ag[16][4];
    {
        const int g = lane >> 2, tg = lane & 3;
        const int r0 = warp * 16 + g;
        #pragma unroll
        for (int kk = 0; kk < 16; ++kk) {
            const int c0 = kk * 8 + tg;
            Ah[kk][0] = f2tf32(h2_w[r0 * 128 + c0]);
            Ah[kk][1] = f2tf32(h2_w[(r0 + 8) * 128 + c0]);
            Ah[kk][2] = f2tf32(h2_w[r0 * 128 + c0 + 4]);
            Ah[kk][3] = f2tf32(h2_w[(r0 + 8) * 128 + c0 + 4]);
            Ag[kk][0] = f2tf32(g2_w[r0 * 128 + c0]);
            Ag[kk][1] = f2tf32(g2_w[(r0 + 8) * 128 + c0]);
            Ag[kk][2] = f2tf32(g2_w[r0 * 128 + c0 + 4]);
            Ag[kk][3] = f2tf32(g2_w[(r0 + 8) * 128 + c0 + 4]);
        }
    }

    // load y0 (x0) for this block's 128 points
    const int p0 = blockIdx.x * TILE;
    for (int i = tid; i < 3 * TILE; i += THREADS) {
        int c = i >> 7, pl = i & 127;
        int pg = p0 + pl;
        float v = 0.f;
        if (pg < P) {
            int b = pg / NPER, n = pg - b * NPER;
            v = x0[(b * 3 + c) * NPER + n];
        }
        y0b[i] = v; yb[i] = v;
    }
    __syncthreads();

    const float third = 1.0f / 3.0f;

    // RK4 3/8 rule
    field_eval(0.0f, yb, k1b, B, Ah, Ag, tid, warp, lane);
    for (int i = tid; i < 384; i += THREADS) yb[i] = y0b[i] + k1b[i] * third;
    __syncthreads();

    field_eval(third, yb, k2b, B, Ah, Ag, tid, warp, lane);
    for (int i = tid; i < 384; i += THREADS) yb[i] = y0b[i] + (k2b[i] - k1b[i] * third);
    __syncthreads();

    field_eval(third * 2.0f, yb, k3b, B, Ah, Ag, tid, warp, lane);
    for (int i = tid; i < 384; i += THREADS) {
        float a = k1b[i], b2 = k2b[i], c3 = k3b[i];
        yb[i]  = y0b[i] + (a - b2 + c3);
        k1b[i] = a + 3.0f * (b2 + c3);   // fold k1 + 3*(k2+k3)
    }
    __syncthreads();

    field_eval(1.0f, yb, k2b, B, Ah, Ag, tid, warp, lane);  // k4 -> k2b

    // out = y0 + (k1 + 3*(k2+k3) + k4) / 8
    for (int i = tid; i < 3 * TILE; i += THREADS) {
        int c = i >> 7, pl = i & 127;
        int pg = p0 + pl;
        if (pg < P) {
            int b = pg / NPER, n = pg - b * NPER;
            yout[(b * 3 + c) * NPER + n] = y0b[i] + (k1b[i] + k2b[i]) * 0.125f;
        }
    }
}

extern "C" void kernel_launch(void* const* d_in, const int* in_sizes, int n_in,
                              void* d_out, int out_size) {
    const float* x0    = (const float*)d_in[0];
    const float* h1_w  = (const float*)d_in[1];
    const float* h1_b  = (const float*)d_in[2];
    const float* g1_w  = (const float*)d_in[3];
    const float* g1_b  = (const float*)d_in[4];
    const float* h2_w  = (const float*)d_in[5];
    const float* h2_b  = (const float*)d_in[6];
    const float* g2_w  = (const float*)d_in[7];
    const float* g2_b  = (const float*)d_in[8];
    const float* out_w = (const float*)d_in[9];
    const float* out_b = (const float*)d_in[10];
    float* yout = (float*)d_out;

    const int P = in_sizes[0] / 3;                 // total points = B*N
    const int blocks = (P + TILE - 1) / TILE;      // 3125
    const size_t smem = SMEM_FLOATS * sizeof(float);

    cudaFuncSetAttribute(node_kernel, cudaFuncAttributeMaxDynamicSharedMemorySize, (int)smem);
    node_kernel<<<blocks, THREADS, smem>>>(x0, h1_w, h1_b, g1_w, g1_b,
                                           h2_w, h2_b, g2_w, g2_b,
                                           out_w, out_b, yout, P);
}

// round 5
// speedup vs baseline: 1.0739x; 1.0739x over previous
#include <cuda_runtime.h>
#include <stdint.h>

#define THREADS 256
#define TILE 128
#define NPER 50000

// Z1: permuted point-major [p][perm(k)], row stride 144 floats.
//   pos(k) = (k&3)*36 + (k>>2)   (sections of 36, data in first 32 of each; 3*36+32=140<=144)
#define Z1_STRIDE 144
// Z2: channel-major [ch][p], stride 132
#define Z2_STRIDE 132

// shared floats: Z1(128*144) + Z2(128*132) + 4 bias vecs(128*4) + ow(384) + ob(4)
//              + y0/y/k1/k2/k3 (384*5)
#define SMEM_FLOATS (128*Z1_STRIDE + 128*Z2_STRIDE + 128*4 + 384 + 4 + 384*5)

static __device__ __forceinline__ uint32_t f2tf32(float x) {
    uint32_t r;
    asm("cvt.rna.tf32.f32 %0, %1;" : "=r"(r) : "f"(x));
    return r;
}

static __device__ __forceinline__ void mma8(float d[4], const uint32_t a[4],
                                            uint32_t b0, uint32_t b1) {
    asm volatile(
        "mma.sync.aligned.m16n8k8.row.col.f32.tf32.tf32.f32 "
        "{%0,%1,%2,%3}, {%4,%5,%6,%7}, {%8,%9}, {%0,%1,%2,%3};\n"
        : "+f"(d[0]), "+f"(d[1]), "+f"(d[2]), "+f"(d[3])
        : "r"(a[0]), "r"(a[1]), "r"(a[2]), "r"(a[3]), "r"(b0), "r"(b1));
}

static __device__ __forceinline__ float fsig(float x) {
    return __fdividef(1.0f, 1.0f + __expf(-x));
}

struct Bufs {
    float *Z1, *Z2, *h2b, *g2b, *ow, *ob;
};

// Per-thread layer-1 weights (thread owns one channel ch = tid&127)
struct L1W {
    float wh0, wh1, wh2, wh3, wg0, wg1, wg2, wg3, bh, bg;
};

// One field evaluation for the block's 128 points: y (shared [3][128]) -> kdst (shared [3][128])
static __device__ __forceinline__ void field_eval(
    float t, const float* __restrict__ yb, float* __restrict__ kdst,
    const Bufs& B, const L1W& W, const uint32_t (&Ah)[16][4], const uint32_t (&Ag)[16][4],
    int tid, int warp, int lane)
{
    // ---- layer 1 (4 -> 128, gated). Thread owns channel ch = tid&127, loops points.
    //      Write z1 (tf32) into permuted layout Z1[p*144 + (ch&3)*36 + (ch>>2)]. ----
    {
        const int ch = tid & 127;
        const int half = tid >> 7;
        const int chOff = (ch & 3) * 36 + (ch >> 2);
        const float bh_t = W.bh + W.wh3 * t;
        const float bg_t = W.bg + W.wg3 * t;
        #pragma unroll 4
        for (int i = 0; i < 64; ++i) {
            const int p = 2 * i + half;
            const float zx = yb[p], zy = yb[128 + p], zz = yb[256 + p]; // warp-broadcast
            float h  = fmaf(W.wh0, zx, fmaf(W.wh1, zy, fmaf(W.wh2, zz, bh_t)));
            float gg = fmaf(W.wg0, zx, fmaf(W.wg1, zy, fmaf(W.wg2, zz, bg_t)));
            float z = fmaxf(h * fsig(gg), 0.0f);
            B.Z1[p * Z1_STRIDE + chOff] = __uint_as_float(f2tf32(z));
        }
    }
    __syncthreads();

    // ---- layer 2: two 128x128x128 GEMMs (h2, g2) on tensor pipe.
    //      B fragments via conflict-free ld.shared.v4 from permuted Z1. ----
    {
        const int g = lane >> 2, tg = lane & 3;
        const int row = warp * 16 + g;
        const float bh0 = B.h2b[row], bh1 = B.h2b[row + 8];
        const float bg0 = B.g2b[row], bg1 = B.g2b[row + 8];
        for (int n0 = 0; n0 < 128; n0 += 8) {
            float dh[4] = {0.f, 0.f, 0.f, 0.f};
            float dg[4] = {0.f, 0.f, 0.f, 0.f};
            const float4* bptr = (const float4*)(B.Z1 + (n0 + g) * Z1_STRIDE + tg * 36);
            #pragma unroll
            for (int c = 0; c < 8; ++c) {
                float4 F = bptr[c];   // (b0_{kk=2c}, b1_{kk=2c}, b0_{kk=2c+1}, b1_{kk=2c+1})
                uint32_t f0 = __float_as_uint(F.x), f1 = __float_as_uint(F.y);
                uint32_t f2 = __float_as_uint(F.z), f3 = __float_as_uint(F.w);
                mma8(dh, Ah[2 * c],     f0, f1);
                mma8(dg, Ag[2 * c],     f0, f1);
                mma8(dh, Ah[2 * c + 1], f2, f3);
                mma8(dg, Ag[2 * c + 1], f2, f3);
            }
            float z00 = fmaxf((dh[0] + bh0) * fsig(dg[0] + bg0), 0.f);
            float z01 = fmaxf((dh[1] + bh0) * fsig(dg[1] + bg0), 0.f);
            float z10 = fmaxf((dh[2] + bh1) * fsig(dg[2] + bg1), 0.f);
            float z11 = fmaxf((dh[3] + bh1) * fsig(dg[3] + bg1), 0.f);
            int col = n0 + 2 * tg;
            *(float2*)(B.Z2 + row       * Z2_STRIDE + col) = make_float2(z00, z01);
            *(float2*)(B.Z2 + (row + 8) * Z2_STRIDE + col) = make_float2(z10, z11);
        }
    }
    __syncthreads();

    // ---- out layer (128 -> 3) + tanh*0.5, 2 threads per point ----
    {
        const int q = tid & 1, p = tid >> 1;
        float d0 = 0.f, d1 = 0.f, d2 = 0.f;
        const int chb = q * 64;
        #pragma unroll 4
        for (int i = 0; i < 64; ++i) {
            int ch = chb + i;
            float z = B.Z2[ch * Z2_STRIDE + p];
            d0 = fmaf(B.ow[ch], z, d0);
            d1 = fmaf(B.ow[128 + ch], z, d1);
            d2 = fmaf(B.ow[256 + ch], z, d2);
        }
        d0 += __shfl_xor_sync(0xffffffffu, d0, 1);
        d1 += __shfl_xor_sync(0xffffffffu, d1, 1);
        d2 += __shfl_xor_sync(0xffffffffu, d2, 1);
        if (q == 0) {
            kdst[p]       = tanhf(d0 + B.ob[0]) * 0.5f;
            kdst[128 + p] = tanhf(d1 + B.ob[1]) * 0.5f;
            kdst[256 + p] = tanhf(d2 + B.ob[2]) * 0.5f;
        }
    }
    __syncthreads();
}

__global__ void __launch_bounds__(THREADS, 1)
node_kernel(const float* __restrict__ x0,
            const float* __restrict__ h1_w, const float* __restrict__ h1_b,
            const float* __restrict__ g1_w, const float* __restrict__ g1_b,
            const float* __restrict__ h2_w, const float* __restrict__ h2_b,
            const float* __restrict__ g2_w, const float* __restrict__ g2_b,
            const float* __restrict__ out_w, const float* __restrict__ out_b,
            float* __restrict__ yout, int P)
{
    extern __shared__ float sm[];
    Bufs B;
    B.Z1  = sm;
    B.Z2  = B.Z1 + 128 * Z1_STRIDE;
    B.h2b = B.Z2 + 128 * Z2_STRIDE;
    B.g2b = B.h2b + 128;
    float* h1bv = B.g2b + 128;
    float* g1bv = h1bv + 128;
    B.ow  = g1bv + 128;
    B.ob  = B.ow + 384;
    float* y0b = B.ob + 4;
    float* yb  = y0b + 384;
    float* k1b = yb  + 384;
    float* k2b = k1b + 384;
    float* k3b = k2b + 384;

    const int tid  = threadIdx.x;
    const int warp = tid >> 5;
    const int lane = tid & 31;

    // stage biases / out weights into shared
    for (int i = tid; i < 128; i += THREADS) {
        B.h2b[i] = h2_b[i]; B.g2b[i] = g2_b[i];
        h1bv[i] = h1_b[i]; g1bv[i] = g1_b[i];
    }
    for (int i = tid; i < 384; i += THREADS) B.ow[i] = out_w[i];
    if (tid < 3) B.ob[tid] = out_b[tid];

    // per-thread layer-1 weights in registers (thread owns channel ch = tid&127)
    L1W W;
    {
        const int ch = tid & 127;
        W.wh0 = h1_w[ch*4+0]; W.wh1 = h1_w[ch*4+1]; W.wh2 = h1_w[ch*4+2]; W.wh3 = h1_w[ch*4+3];
        W.wg0 = g1_w[ch*4+0]; W.wg1 = g1_w[ch*4+1]; W.wg2 = g1_w[ch*4+2]; W.wg3 = g1_w[ch*4+3];
        W.bh  = h1_b[ch];     W.bg  = g1_b[ch];
    }

    // A fragments (tf32) for h2 and g2: K=128 -> 16 k-steps, warp owns rows [warp*16, warp*16+16)
    uint32_t Ah[16][4], Ag[16][4];
    {
        const int g = lane >> 2, tg = lane & 3;
        const int r0 = warp * 16 + g;
        #pragma unroll
        for (int kk = 0; kk < 16; ++kk) {
            const int c0 = kk * 8 + tg;
            Ah[kk][0] = f2tf32(h2_w[r0 * 128 + c0]);
            Ah[kk][1] = f2tf32(h2_w[(r0 + 8) * 128 + c0]);
            Ah[kk][2] = f2tf32(h2_w[r0 * 128 + c0 + 4]);
            Ah[kk][3] = f2tf32(h2_w[(r0 + 8) * 128 + c0 + 4]);
            Ag[kk][0] = f2tf32(g2_w[r0 * 128 + c0]);
            Ag[kk][1] = f2tf32(g2_w[(r0 + 8) * 128 + c0]);
            Ag[kk][2] = f2tf32(g2_w[r0 * 128 + c0 + 4]);
            Ag[kk][3] = f2tf32(g2_w[(r0 + 8) * 128 + c0 + 4]);
        }
    }

    // load y0 (x0) for this block's 128 points
    const int p0 = blockIdx.x * TILE;
    for (int i = tid; i < 3 * TILE; i += THREADS) {
        int c = i >> 7, pl = i & 127;
        int pg = p0 + pl;
        float v = 0.f;
        if (pg < P) {
            int b = pg / NPER, n = pg - b * NPER;
            v = x0[(b * 3 + c) * NPER + n];
        }
        y0b[i] = v; yb[i] = v;
    }
    __syncthreads();

    const float third = 1.0f / 3.0f;

    // RK4 3/8 rule
    field_eval(0.0f, yb, k1b, B, W, Ah, Ag, tid, warp, lane);
    for (int i = tid; i < 384; i += THREADS) yb[i] = y0b[i] + k1b[i] * third;
    __syncthreads();

    field_eval(third, yb, k2b, B, W, Ah, Ag, tid, warp, lane);
    for (int i = tid; i < 384; i += THREADS) yb[i] = y0b[i] + (k2b[i] - k1b[i] * third);
    __syncthreads();

    field_eval(third * 2.0f, yb, k3b, B, W, Ah, Ag, tid, warp, lane);
    for (int i = tid; i < 384; i += THREADS) {
        float a = k1b[i], b2 = k2b[i], c3 = k3b[i];
        yb[i]  = y0b[i] + (a - b2 + c3);
        k1b[i] = a + 3.0f * (b2 + c3);   // fold k1 + 3*(k2+k3)
    }
    __syncthreads();

    field_eval(1.0f, yb, k2b, B, W, Ah, Ag, tid, warp, lane);  // k4 -> k2b

    // out = y0 + (k1 + 3*(k2+k3) + k4) / 8
    for (int i = tid; i < 3 * TILE; i += THREADS) {
        int c = i >> 7, pl = i & 127;
        int pg = p0 + pl;
        if (pg < P) {
            int b = pg / NPER, n = pg - b * NPER;
            yout[(b * 3 + c) * NPER + n] = y0b[i] + (k1b[i] + k2b[i]) * 0.125f;
        }
    }
}

extern "C" void kernel_launch(void* const* d_in, const int* in_sizes, int n_in,
                              void* d_out, int out_size) {
    const float* x0    = (const float*)d_in[0];
    const float* h1_w  = (const float*)d_in[1];
    const float* h1_b  = (const float*)d_in[2];
    const float* g1_w  = (const float*)d_in[3];
    const float* g1_b  = (const float*)d_in[4];
    const float* h2_w  = (const float*)d_in[5];
    const float* h2_b  = (const float*)d_in[6];
    const float* g2_w  = (const float*)d_in[7];
    const float* g2_b  = (const float*)d_in[8];
    const float* out_w = (const float*)d_in[9];
    const float* out_b = (const float*)d_in[10];
    float* yout = (float*)d_out;

    const int P = in_sizes[0] / 3;                 // total points = B*N
    const int blocks = (P + TILE - 1) / TILE;      // 3125
    const size_t smem = SMEM_FLOATS * sizeof(float);

    cudaFuncSetAttribute(node_kernel, cudaFuncAttributeMaxDynamicSharedMemorySize, (int)smem);
    node_kernel<<<blocks, THREADS, smem>>>(x0, h1_w, h1_b, g1_w, g1_b,
                                           h2_w, h2_b, g2_w, g2_b,
                                           out_w, out_b, yout, P);
}

// round 6
// speedup vs baseline: 1.1315x; 1.0536x over previous
#include <cuda_runtime.h>
#include <stdint.h>

#define THREADS 256
#define TILE 128
#define NPER 50000

// Z1: permuted point-major [p][perm(k)], row stride 144 floats.
//   pos(k) = (k&3)*36 + (k>>2)
#define Z1_STRIDE 144
// Wpart: per-warp out-layer partials [8 warps][3 outs][128 pts]
#define WP_OSTRIDE 136
#define WP_WSTRIDE (3*WP_OSTRIDE)   // 408

// shared floats: Z1(128*144) + Wpart(8*408) + h2b/g2b(256) + ob(4) + y bufs(384*5)
#define SMEM_FLOATS (128*Z1_STRIDE + 8*WP_WSTRIDE + 256 + 4 + 384*5)

static __device__ __forceinline__ uint32_t f2tf32(float x) {
    uint32_t r;
    asm("cvt.rna.tf32.f32 %0, %1;" : "=r"(r) : "f"(x));
    return r;
}

static __device__ __forceinline__ float tanha(float x) {
    float r;
    asm("tanh.approx.f32 %0, %1;" : "=f"(r) : "f"(x));
    return r;
}

// sigmoid(x) = 0.5*tanh(0.5x) + 0.5  (single MUFU)
static __device__ __forceinline__ float fsig(float x) {
    return fmaf(tanha(0.5f * x), 0.5f, 0.5f);
}

static __device__ __forceinline__ void mma8(float d[4], const uint32_t a[4],
                                            uint32_t b0, uint32_t b1) {
    asm volatile(
        "mma.sync.aligned.m16n8k8.row.col.f32.tf32.tf32.f32 "
        "{%0,%1,%2,%3}, {%4,%5,%6,%7}, {%8,%9}, {%0,%1,%2,%3};\n"
        : "+f"(d[0]), "+f"(d[1]), "+f"(d[2]), "+f"(d[3])
        : "r"(a[0]), "r"(a[1]), "r"(a[2]), "r"(a[3]), "r"(b0), "r"(b1));
}

struct Bufs {
    float *Z1, *WP, *h2b, *g2b, *ob;
};

// Per-thread layer-1 weights (thread owns one channel ch = tid&127)
struct L1W {
    float wh0, wh1, wh2, wh3, wg0, wg1, wg2, wg3, bh, bg;
};
// Per-thread out-layer weights for this thread's two GEMM rows
struct OW {
    float o0a, o0b, o1a, o1b, o2a, o2b;
};

// One field evaluation for the block's 128 points: y (shared [3][128]) -> kdst (shared [3][128])
static __device__ __forceinline__ void field_eval(
    float t, const float* __restrict__ yb, float* __restrict__ kdst,
    const Bufs& B, const L1W& W, const OW& O,
    const uint32_t (&Ah)[16][4], const uint32_t (&Ag)[16][4],
    int tid, int warp, int lane)
{
    // ---- layer 1 (4 -> 128, gated). Thread owns channel ch = tid&127, loops points. ----
    {
        const int ch = tid & 127;
        const int half = tid >> 7;
        const int chOff = (ch & 3) * 36 + (ch >> 2);
        const float bh_t = W.bh + W.wh3 * t;
        const float bg_t = W.bg + W.wg3 * t;
        #pragma unroll 4
        for (int i = 0; i < 64; ++i) {
            const int p = 2 * i + half;
            const float zx = yb[p], zy = yb[128 + p], zz = yb[256 + p]; // warp-broadcast
            float h  = fmaf(W.wh0, zx, fmaf(W.wh1, zy, fmaf(W.wh2, zz, bh_t)));
            float gg = fmaf(W.wg0, zx, fmaf(W.wg1, zy, fmaf(W.wg2, zz, bg_t)));
            float z = fmaxf(h * fsig(gg), 0.0f);
            B.Z1[p * Z1_STRIDE + chOff] = __uint_as_float(f2tf32(z));
        }
    }
    __syncthreads();

    // ---- layer 2: two 128x128x128 GEMMs (h2, g2) on tensor pipe; gate-combine in regs;
    //      out-layer fused: per-warp partial column sums via shfl reduce -> Wpart. ----
    {
        const int g = lane >> 2, tg = lane & 3;
        const int row = warp * 16 + g;
        const float bh0 = B.h2b[row], bh1 = B.h2b[row + 8];
        const float bg0 = B.g2b[row], bg1 = B.g2b[row + 8];
        float* wpw = B.WP + warp * WP_WSTRIDE;

        #pragma unroll 2
        for (int n0 = 0; n0 < 128; n0 += 8) {
            float dh[4] = {0.f, 0.f, 0.f, 0.f};
            float dg[4] = {0.f, 0.f, 0.f, 0.f};
            const float4* bptr = (const float4*)(B.Z1 + (n0 + g) * Z1_STRIDE + tg * 36);
            #pragma unroll
            for (int c = 0; c < 8; ++c) {
                float4 F = bptr[c];
                uint32_t f0 = __float_as_uint(F.x), f1 = __float_as_uint(F.y);
                uint32_t f2 = __float_as_uint(F.z), f3 = __float_as_uint(F.w);
                mma8(dh, Ah[2 * c],     f0, f1);
                mma8(dg, Ag[2 * c],     f0, f1);
                mma8(dh, Ah[2 * c + 1], f2, f3);
                mma8(dg, Ag[2 * c + 1], f2, f3);
            }
            float z00 = fmaxf((dh[0] + bh0) * fsig(dg[0] + bg0), 0.f);
            float z01 = fmaxf((dh[1] + bh0) * fsig(dg[1] + bg0), 0.f);
            float z10 = fmaxf((dh[2] + bh1) * fsig(dg[2] + bg1), 0.f);
            float z11 = fmaxf((dh[3] + bh1) * fsig(dg[3] + bg1), 0.f);

            // fused out-layer: partial sums over this warp's 16 rows for cols (n0+2tg, +1)
            float s0a = fmaf(O.o0a, z00, O.o0b * z10);
            float s0b = fmaf(O.o0a, z01, O.o0b * z11);
            float s1a = fmaf(O.o1a, z00, O.o1b * z10);
            float s1b = fmaf(O.o1a, z01, O.o1b * z11);
            float s2a = fmaf(O.o2a, z00, O.o2b * z10);
            float s2b = fmaf(O.o2a, z01, O.o2b * z11);
            #pragma unroll
            for (int m = 4; m < 32; m <<= 1) {
                s0a += __shfl_xor_sync(0xffffffffu, s0a, m);
                s0b += __shfl_xor_sync(0xffffffffu, s0b, m);
                s1a += __shfl_xor_sync(0xffffffffu, s1a, m);
                s1b += __shfl_xor_sync(0xffffffffu, s1b, m);
                s2a += __shfl_xor_sync(0xffffffffu, s2a, m);
                s2b += __shfl_xor_sync(0xffffffffu, s2b, m);
            }
            if (g < 3) {
                float sa = (g == 0) ? s0a : ((g == 1) ? s1a : s2a);
                float sb = (g == 0) ? s0b : ((g == 1) ? s1b : s2b);
                *(float2*)(wpw + g * WP_OSTRIDE + n0 + 2 * tg) = make_float2(sa, sb);
            }
        }
    }
    __syncthreads();

    // ---- reduce per-warp partials -> kdst (tanh * 0.5), 384 outputs ----
    for (int i = tid; i < 384; i += THREADS) {
        const int c = i >> 7, p = i & 127;
        float s = B.ob[c];
        const float* wp = B.WP + c * WP_OSTRIDE + p;
        #pragma unroll
        for (int w = 0; w < 8; ++w) s += wp[w * WP_WSTRIDE];
        kdst[i] = tanhf(s) * 0.5f;
    }
    __syncthreads();
}

__global__ void __launch_bounds__(THREADS, 1)
node_kernel(const float* __restrict__ x0,
            const float* __restrict__ h1_w, const float* __restrict__ h1_b,
            const float* __restrict__ g1_w, const float* __restrict__ g1_b,
            const float* __restrict__ h2_w, const float* __restrict__ h2_b,
            const float* __restrict__ g2_w, const float* __restrict__ g2_b,
            const float* __restrict__ out_w, const float* __restrict__ out_b,
            float* __restrict__ yout, int P)
{
    extern __shared__ float sm[];
    Bufs B;
    B.Z1  = sm;
    B.WP  = B.Z1 + 128 * Z1_STRIDE;
    B.h2b = B.WP + 8 * WP_WSTRIDE;
    B.g2b = B.h2b + 128;
    B.ob  = B.g2b + 128;
    float* y0b = B.ob + 4;
    float* yb  = y0b + 384;
    float* k1b = yb  + 384;
    float* k2b = k1b + 384;
    float* k3b = k2b + 384;

    const int tid  = threadIdx.x;
    const int warp = tid >> 5;
    const int lane = tid & 31;

    // stage biases into shared
    for (int i = tid; i < 128; i += THREADS) { B.h2b[i] = h2_b[i]; B.g2b[i] = g2_b[i]; }
    if (tid < 3) B.ob[tid] = out_b[tid];

    // per-thread layer-1 weights in registers (thread owns channel ch = tid&127)
    L1W W;
    {
        const int ch = tid & 127;
        W.wh0 = h1_w[ch*4+0]; W.wh1 = h1_w[ch*4+1]; W.wh2 = h1_w[ch*4+2]; W.wh3 = h1_w[ch*4+3];
        W.wg0 = g1_w[ch*4+0]; W.wg1 = g1_w[ch*4+1]; W.wg2 = g1_w[ch*4+2]; W.wg3 = g1_w[ch*4+3];
        W.bh  = h1_b[ch];     W.bg  = g1_b[ch];
    }

    // per-thread out-layer weights for rows (row, row+8)
    OW O;
    {
        const int row = warp * 16 + ((lane >> 2));
        O.o0a = out_w[row];        O.o0b = out_w[row + 8];
        O.o1a = out_w[128 + row];  O.o1b = out_w[128 + row + 8];
        O.o2a = out_w[256 + row];  O.o2b = out_w[256 + row + 8];
    }

    // A fragments (tf32) for h2 and g2: K=128 -> 16 k-steps, warp owns rows [warp*16, +16)
    uint32_t Ah[16][4], Ag[16][4];
    {
        const int g = lane >> 2, tg = lane & 3;
        const int r0 = warp * 16 + g;
        #pragma unroll
        for (int kk = 0; kk < 16; ++kk) {
            const int c0 = kk * 8 + tg;
            Ah[kk][0] = f2tf32(h2_w[r0 * 128 + c0]);
            Ah[kk][1] = f2tf32(h2_w[(r0 + 8) * 128 + c0]);
            Ah[kk][2] = f2tf32(h2_w[r0 * 128 + c0 + 4]);
            Ah[kk][3] = f2tf32(h2_w[(r0 + 8) * 128 + c0 + 4]);
            Ag[kk][0] = f2tf32(g2_w[r0 * 128 + c0]);
            Ag[kk][1] = f2tf32(g2_w[(r0 + 8) * 128 + c0]);
            Ag[kk][2] = f2tf32(g2_w[r0 * 128 + c0 + 4]);
            Ag[kk][3] = f2tf32(g2_w[(r0 + 8) * 128 + c0 + 4]);
        }
    }

    // load y0 (x0) for this block's 128 points
    const int p0 = blockIdx.x * TILE;
    for (int i = tid; i < 3 * TILE; i += THREADS) {
        int c = i >> 7, pl = i & 127;
        int pg = p0 + pl;
        float v = 0.f;
        if (pg < P) {
            int b = pg / NPER, n = pg - b * NPER;
            v = x0[(b * 3 + c) * NPER + n];
        }
        y0b[i] = v; yb[i] = v;
    }
    __syncthreads();

    const float third = 1.0f / 3.0f;

    // RK4 3/8 rule
    field_eval(0.0f, yb, k1b, B, W, O, Ah, Ag, tid, warp, lane);
    for (int i = tid; i < 384; i += THREADS) yb[i] = y0b[i] + k1b[i] * third;
    __syncthreads();

    field_eval(third, yb, k2b, B, W, O, Ah, Ag, tid, warp, lane);
    for (int i = tid; i < 384; i += THREADS) yb[i] = y0b[i] + (k2b[i] - k1b[i] * third);
    __syncthreads();

    field_eval(third * 2.0f, yb, k3b, B, W, O, Ah, Ag, tid, warp, lane);
    for (int i = tid; i < 384; i += THREADS) {
        float a = k1b[i], b2 = k2b[i], c3 = k3b[i];
        yb[i]  = y0b[i] + (a - b2 + c3);
        k1b[i] = a + 3.0f * (b2 + c3);   // fold k1 + 3*(k2+k3)
    }
    __syncthreads();

    field_eval(1.0f, yb, k2b, B, W, O, Ah, Ag, tid, warp, lane);  // k4 -> k2b

    // out = y0 + (k1 + 3*(k2+k3) + k4) / 8
    for (int i = tid; i < 3 * TILE; i += THREADS) {
        int c = i >> 7, pl = i & 127;
        int pg = p0 + pl;
        if (pg < P) {
            int b = pg / NPER, n = pg - b * NPER;
            yout[(b * 3 + c) * NPER + n] = y0b[i] + (k1b[i] + k2b[i]) * 0.125f;
        }
    }
}

extern "C" void kernel_launch(void* const* d_in, const int* in_sizes, int n_in,
                              void* d_out, int out_size) {
    const float* x0    = (const float*)d_in[0];
    const float* h1_w  = (const float*)d_in[1];
    const float* h1_b  = (const float*)d_in[2];
    const float* g1_w  = (const float*)d_in[3];
    const float* g1_b  = (const float*)d_in[4];
    const float* h2_w  = (const float*)d_in[5];
    const float* h2_b  = (const float*)d_in[6];
    const float* g2_w  = (const float*)d_in[7];
    const float* g2_b  = (const float*)d_in[8];
    const float* out_w = (const float*)d_in[9];
    const float* out_b = (const float*)d_in[10];
    float* yout = (float*)d_out;

    const int P = in_sizes[0] / 3;                 // total points = B*N
    const int blocks = (P + TILE - 1) / TILE;      // 3125
    const size_t smem = SMEM_FLOATS * sizeof(float);

    cudaFuncSetAttribute(node_kernel, cudaFuncAttributeMaxDynamicSharedMemorySize, (int)smem);
    node_kernel<<<blocks, THREADS, smem>>>(x0, h1_w, h1_b, g1_w, g1_b,
                                           h2_w, h2_b, g2_w, g2_b,
                                           out_w, out_b, yout, P);
}

// round 7
// speedup vs baseline: 2.0592x; 1.8199x over previous
#include <cuda_runtime.h>
#include <cuda_bf16.h>
#include <stdint.h>

#define THREADS 256
#define TILE 128
#define NPER 50000

// Z1: bf16x2 words, point-major, row stride 72 words (64 data + 8 pad).
//   Within k-step s (K=16, 8 words), word w_local stored at pos 2*(w&3) + (w>>2).
//   Thread tg's (b0,b1) for step s = one LDS.64 at byte  p*288 + s*32 + tg*8.
#define Z1_WSTRIDE 72
// Wpart: per-warp out-layer partials [8 warps][3 outs][128 pts]
#define WP_OSTRIDE 136
#define WP_WSTRIDE (3*WP_OSTRIDE)   // 408

// shared floats: Z1(128*72 words) + Wpart(8*408) + h2b/g2b(256) + ob(4) + y bufs(384*5)
#define SMEM_FLOATS (128*Z1_WSTRIDE + 8*WP_WSTRIDE + 256 + 4 + 384*5)

static __device__ __forceinline__ float tanha(float x) {
    float r;
    asm("tanh.approx.f32 %0, %1;" : "=f"(r) : "f"(x));
    return r;
}

// sigmoid(x) = 0.5*tanh(0.5x) + 0.5  (single MUFU)
static __device__ __forceinline__ float fsig(float x) {
    return fmaf(tanha(0.5f * x), 0.5f, 0.5f);
}

static __device__ __forceinline__ uint32_t pack_bf2(float lo, float hi) {
    __nv_bfloat162 v = __floats2bfloat162_rn(lo, hi);
    return *(uint32_t*)&v;
}

static __device__ __forceinline__ void mma16(float d[4], const uint32_t a[4],
                                             uint32_t b0, uint32_t b1) {
    asm volatile(
        "mma.sync.aligned.m16n8k16.row.col.f32.bf16.bf16.f32 "
        "{%0,%1,%2,%3}, {%4,%5,%6,%7}, {%8,%9}, {%0,%1,%2,%3};\n"
        : "+f"(d[0]), "+f"(d[1]), "+f"(d[2]), "+f"(d[3])
        : "r"(a[0]), "r"(a[1]), "r"(a[2]), "r"(a[3]), "r"(b0), "r"(b1));
}

struct Bufs {
    uint32_t *Z1;
    float *WP, *h2b, *g2b, *ob;
};

// Per-thread layer-1 weights (thread owns one channel ch = tid&127)
struct L1W {
    float wh0, wh1, wh2, wh3, wg0, wg1, wg2, wg3, bh, bg;
};
// Per-thread out-layer weights for this thread's two GEMM rows
struct OW {
    float o0a, o0b, o1a, o1b, o2a, o2b;
};

// One field evaluation for the block's 128 points: y (shared [3][128]) -> kdst (shared [3][128])
static __device__ __forceinline__ void field_eval(
    float t, const float* __restrict__ yb, float* __restrict__ kdst,
    const Bufs& B, const L1W& W, const OW& O,
    const uint32_t (&Ah)[8][4], const uint32_t (&Ag)[8][4],
    int tid, int warp, int lane)
{
    // ---- layer 1 (4 -> 128, gated). Thread owns channel ch = tid&127, loops points.
    //      Write z1 as bf16 into permuted word layout. ----
    {
        const int ch = tid & 127;
        const int half = tid >> 7;
        const int w = ch >> 1;
        const int posByte = (8 * (w >> 3) + 2 * (w & 3) + ((w >> 2) & 1)) * 4 + (ch & 1) * 2;
        char* z1c = (char*)B.Z1 + posByte;
        const float bh_t = W.bh + W.wh3 * t;
        const float bg_t = W.bg + W.wg3 * t;
        #pragma unroll 4
        for (int i = 0; i < 64; ++i) {
            const int p = 2 * i + half;
            const float zx = yb[p], zy = yb[128 + p], zz = yb[256 + p]; // warp-broadcast
            float h  = fmaf(W.wh0, zx, fmaf(W.wh1, zy, fmaf(W.wh2, zz, bh_t)));
            float gg = fmaf(W.wg0, zx, fmaf(W.wg1, zy, fmaf(W.wg2, zz, bg_t)));
            float z = fmaxf(h * fsig(gg), 0.0f);
            *(__nv_bfloat16*)(z1c + p * (Z1_WSTRIDE * 4)) = __float2bfloat16(z);
        }
    }
    __syncthreads();

    // ---- layer 2: two 128x128x128 bf16 GEMMs on tensor pipe; gate-combine in regs;
    //      fused out-layer partials via shfl reduce -> Wpart. ----
    {
        const int g = lane >> 2, tg = lane & 3;
        const int row = warp * 16 + g;
        const float bh0 = B.h2b[row], bh1 = B.h2b[row + 8];
        const float bg0 = B.g2b[row], bg1 = B.g2b[row + 8];
        float* wpw = B.WP + warp * WP_WSTRIDE;

        #pragma unroll 2
        for (int n0 = 0; n0 < 128; n0 += 8) {
            float dh[4] = {0.f, 0.f, 0.f, 0.f};
            float dg[4] = {0.f, 0.f, 0.f, 0.f};
            const uint2* bptr = (const uint2*)((const char*)B.Z1
                                + (n0 + g) * (Z1_WSTRIDE * 4) + tg * 8);
            #pragma unroll
            for (int s = 0; s < 8; ++s) {
                uint2 bb = bptr[s * 4];   // 32B per k-step block
                mma16(dh, Ah[s], bb.x, bb.y);
                mma16(dg, Ag[s], bb.x, bb.y);
            }
            float z00 = fmaxf((dh[0] + bh0) * fsig(dg[0] + bg0), 0.f);
            float z01 = fmaxf((dh[1] + bh0) * fsig(dg[1] + bg0), 0.f);
            float z10 = fmaxf((dh[2] + bh1) * fsig(dg[2] + bg1), 0.f);
            float z11 = fmaxf((dh[3] + bh1) * fsig(dg[3] + bg1), 0.f);

            // fused out-layer: partial sums over this warp's 16 rows for cols (n0+2tg, +1)
            float s0a = fmaf(O.o0a, z00, O.o0b * z10);
            float s0b = fmaf(O.o0a, z01, O.o0b * z11);
            float s1a = fmaf(O.o1a, z00, O.o1b * z10);
            float s1b = fmaf(O.o1a, z01, O.o1b * z11);
            float s2a = fmaf(O.o2a, z00, O.o2b * z10);
            float s2b = fmaf(O.o2a, z01, O.o2b * z11);
            #pragma unroll
            for (int m = 4; m < 32; m <<= 1) {
                s0a += __shfl_xor_sync(0xffffffffu, s0a, m);
                s0b += __shfl_xor_sync(0xffffffffu, s0b, m);
                s1a += __shfl_xor_sync(0xffffffffu, s1a, m);
                s1b += __shfl_xor_sync(0xffffffffu, s1b, m);
                s2a += __shfl_xor_sync(0xffffffffu, s2a, m);
                s2b += __shfl_xor_sync(0xffffffffu, s2b, m);
            }
            if (g < 3) {
                float sa = (g == 0) ? s0a : ((g == 1) ? s1a : s2a);
                float sb = (g == 0) ? s0b : ((g == 1) ? s1b : s2b);
                *(float2*)(wpw + g * WP_OSTRIDE + n0 + 2 * tg) = make_float2(sa, sb);
            }
        }
    }
    __syncthreads();

    // ---- reduce per-warp partials -> kdst (tanh * 0.5), 384 outputs ----
    for (int i = tid; i < 384; i += THREADS) {
        const int c = i >> 7, p = i & 127;
        float s = B.ob[c];
        const float* wp = B.WP + c * WP_OSTRIDE + p;
        #pragma unroll
        for (int w = 0; w < 8; ++w) s += wp[w * WP_WSTRIDE];
        kdst[i] = tanhf(s) * 0.5f;
    }
    __syncthreads();
}

__global__ void __launch_bounds__(THREADS, 2)
node_kernel(const float* __restrict__ x0,
            const float* __restrict__ h1_w, const float* __restrict__ h1_b,
            const float* __restrict__ g1_w, const float* __restrict__ g1_b,
            const float* __restrict__ h2_w, const float* __restrict__ h2_b,
            const float* __restrict__ g2_w, const float* __restrict__ g2_b,
            const float* __restrict__ out_w, const float* __restrict__ out_b,
            float* __restrict__ yout, int P)
{
    extern __shared__ float sm[];
    Bufs B;
    B.Z1  = (uint32_t*)sm;
    B.WP  = sm + 128 * Z1_WSTRIDE;
    B.h2b = B.WP + 8 * WP_WSTRIDE;
    B.g2b = B.h2b + 128;
    B.ob  = B.g2b + 128;
    float* y0b = B.ob + 4;
    float* yb  = y0b + 384;
    float* k1b = yb  + 384;
    float* k2b = k1b + 384;
    float* k3b = k2b + 384;

    const int tid  = threadIdx.x;
    const int warp = tid >> 5;
    const int lane = tid & 31;

    // stage biases into shared
    for (int i = tid; i < 128; i += THREADS) { B.h2b[i] = h2_b[i]; B.g2b[i] = g2_b[i]; }
    if (tid < 3) B.ob[tid] = out_b[tid];

    // per-thread layer-1 weights in registers (thread owns channel ch = tid&127)
    L1W W;
    {
        const int ch = tid & 127;
        W.wh0 = h1_w[ch*4+0]; W.wh1 = h1_w[ch*4+1]; W.wh2 = h1_w[ch*4+2]; W.wh3 = h1_w[ch*4+3];
        W.wg0 = g1_w[ch*4+0]; W.wg1 = g1_w[ch*4+1]; W.wg2 = g1_w[ch*4+2]; W.wg3 = g1_w[ch*4+3];
        W.bh  = h1_b[ch];     W.bg  = g1_b[ch];
    }

    // per-thread out-layer weights for rows (row, row+8)
    OW O;
    {
        const int row = warp * 16 + (lane >> 2);
        O.o0a = out_w[row];        O.o0b = out_w[row + 8];
        O.o1a = out_w[128 + row];  O.o1b = out_w[128 + row + 8];
        O.o2a = out_w[256 + row];  O.o2b = out_w[256 + row + 8];
    }

    // A fragments (bf16, m16n8k16): K=128 -> 8 k-steps, warp owns rows [warp*16, +16)
    uint32_t Ah[8][4], Ag[8][4];
    {
        const int g = lane >> 2, tg = lane & 3;
        const int r0 = warp * 16 + g;
        #pragma unroll
        for (int s = 0; s < 8; ++s) {
            const int k0 = 16 * s + 2 * tg;
            Ah[s][0] = pack_bf2(h2_w[r0 * 128 + k0],           h2_w[r0 * 128 + k0 + 1]);
            Ah[s][1] = pack_bf2(h2_w[(r0 + 8) * 128 + k0],     h2_w[(r0 + 8) * 128 + k0 + 1]);
            Ah[s][2] = pack_bf2(h2_w[r0 * 128 + k0 + 8],       h2_w[r0 * 128 + k0 + 9]);
            Ah[s][3] = pack_bf2(h2_w[(r0 + 8) * 128 + k0 + 8], h2_w[(r0 + 8) * 128 + k0 + 9]);
            Ag[s][0] = pack_bf2(g2_w[r0 * 128 + k0],           g2_w[r0 * 128 + k0 + 1]);
            Ag[s][1] = pack_bf2(g2_w[(r0 + 8) * 128 + k0],     g2_w[(r0 + 8) * 128 + k0 + 1]);
            Ag[s][2] = pack_bf2(g2_w[r0 * 128 + k0 + 8],       g2_w[r0 * 128 + k0 + 9]);
            Ag[s][3] = pack_bf2(g2_w[(r0 + 8) * 128 + k0 + 8], g2_w[(r0 + 8) * 128 + k0 + 9]);
        }
    }

    // load y0 (x0) for this block's 128 points
    const int p0 = blockIdx.x * TILE;
    for (int i = tid; i < 3 * TILE; i += THREADS) {
        int c = i >> 7, pl = i & 127;
        int pg = p0 + pl;
        float v = 0.f;
        if (pg < P) {
            int b = pg / NPER, n = pg - b * NPER;
            v = x0[(b * 3 + c) * NPER + n];
        }
        y0b[i] = v; yb[i] = v;
    }
    __syncthreads();

    const float third = 1.0f / 3.0f;

    // RK4 3/8 rule
    field_eval(0.0f, yb, k1b, B, W, O, Ah, Ag, tid, warp, lane);
    for (int i = tid; i < 384; i += THREADS) yb[i] = y0b[i] + k1b[i] * third;
    __syncthreads();

    field_eval(third, yb, k2b, B, W, O, Ah, Ag, tid, warp, lane);
    for (int i = tid; i < 384; i += THREADS) yb[i] = y0b[i] + (k2b[i] - k1b[i] * third);
    __syncthreads();

    field_eval(third * 2.0f, yb, k3b, B, W, O, Ah, Ag, tid, warp, lane);
    for (int i = tid; i < 384; i += THREADS) {
        float a = k1b[i], b2 = k2b[i], c3 = k3b[i];
        yb[i]  = y0b[i] + (a - b2 + c3);
        k1b[i] = a + 3.0f * (b2 + c3);   // fold k1 + 3*(k2+k3)
    }
    __syncthreads();

    field_eval(1.0f, yb, k2b, B, W, O, Ah, Ag, tid, warp, lane);  // k4 -> k2b

    // out = y0 + (k1 + 3*(k2+k3) + k4) / 8
    for (int i = tid; i < 3 * TILE; i += THREADS) {
        int c = i >> 7, pl = i & 127;
        int pg = p0 + pl;
        if (pg < P) {
            int b = pg / NPER, n = pg - b * NPER;
            yout[(b * 3 + c) * NPER + n] = y0b[i] + (k1b[i] + k2b[i]) * 0.125f;
        }
    }
}

extern "C" void kernel_launch(void* const* d_in, const int* in_sizes, int n_in,
                              void* d_out, int out_size) {
    const float* x0    = (const float*)d_in[0];
    const float* h1_w  = (const float*)d_in[1];
    const float* h1_b  = (const float*)d_in[2];
    const float* g1_w  = (const float*)d_in[3];
    const float* g1_b  = (const float*)d_in[4];
    const float* h2_w  = (const float*)d_in[5];
    const float* h2_b  = (const float*)d_in[6];
    const float* g2_w  = (const float*)d_in[7];
    const float* g2_b  = (const float*)d_in[8];
    const float* out_w = (const float*)d_in[9];
    const float* out_b = (const float*)d_in[10];
    float* yout = (float*)d_out;

    const int P = in_sizes[0] / 3;                 // total points = B*N
    const int blocks = (P + TILE - 1) / TILE;      // 3125
    const size_t smem = SMEM_FLOATS * sizeof(float);

    cudaFuncSetAttribute(node_kernel, cudaFuncAttributeMaxDynamicSharedMemorySize, (int)smem);
    node_kernel<<<blocks, THREADS, smem>>>(x0, h1_w, h1_b, g1_w, g1_b,
                                           h2_w, h2_b, g2_w, g2_b,
                                           out_w, out_b, yout, P);
}

// round 10
// speedup vs baseline: 2.2567x; 1.0959x over previous
#include <cuda_runtime.h>
#include <cuda_bf16.h>
#include <stdint.h>

#define THREADS 256
#define TILE 128
#define NPER 50000

// Z1: 4 k-planes (each covers 2 k-steps = 32 channels). Plane holds 128 points x 64B.
//   Within a point's 64B: tg*16 + (s&1)*8 + half*4  (half: b0 vs b1 word).
//   Plane stride padded +64B so L1-phase stores are conflict-free across planes.
#define PLANE_BYTES 8256
#define Z1_FLOATS (4 * PLANE_BYTES / 4)      // 8256 floats
// Wpart: [8 warps][2 g-halves][3 outs][128 pts (+pad)]
#define WP_OSTRIDE 136
#define WP_HSTRIDE (3 * WP_OSTRIDE)          // 408
#define WP_WSTRIDE (2 * WP_HSTRIDE)          // 816
#define WP_FLOATS  (8 * WP_WSTRIDE)          // 6528
#define YBUF 512                              // 128 points x float4

#define SMEM_FLOATS (Z1_FLOATS + WP_FLOATS + 5*YBUF + 256 + 4)

static __device__ __forceinline__ float tanha(float x) {
    float r;
    asm("tanh.approx.f32 %0, %1;" : "=f"(r) : "f"(x));
    return r;
}
// sigmoid(x) = 0.5*tanh(0.5x) + 0.5 (single MUFU)
static __device__ __forceinline__ float fsig(float x) {
    return fmaf(tanha(0.5f * x), 0.5f, 0.5f);
}
static __device__ __forceinline__ uint32_t pack_bf2(float lo, float hi) {
    __nv_bfloat162 v = __floats2bfloat162_rn(lo, hi);
    return *(uint32_t*)&v;
}
static __device__ __forceinline__ void mma16(float d[4], const uint32_t a[4],
                                             uint32_t b0, uint32_t b1) {
    asm volatile(
        "mma.sync.aligned.m16n8k16.row.col.f32.bf16.bf16.f32 "
        "{%0,%1,%2,%3}, {%4,%5,%6,%7}, {%8,%9}, {%0,%1,%2,%3};\n"
        : "+f"(d[0]), "+f"(d[1]), "+f"(d[2]), "+f"(d[3])
        : "r"(a[0]), "r"(a[1]), "r"(a[2]), "r"(a[3]), "r"(b0), "r"(b1));
}

struct Bufs {
    char  *Z1;
    float *WP, *h2b, *g2b, *ob;
};
// Layer-1 weights for this thread's TWO channels (ch0=2w, ch1=2w+1)
struct L1W {
    float wh0[4], wg0[4], bh0, bg0;
    float wh1[4], wg1[4], bh1, bg1;
};
// Out-layer weights for this thread's two GEMM rows
struct OW {
    float o0a, o0b, o1a, o1b, o2a, o2b;
};

// One field evaluation: y (shared [p][4]) -> kdst (shared [p][4], xyz only)
static __device__ __forceinline__ void field_eval(
    float t, const float* __restrict__ yb, float* __restrict__ kdst,
    const Bufs& B, const L1W& W, const OW& O, char* __restrict__ z1wr,
    const uint32_t (&Ah)[8][4], const uint32_t (&Ag)[8][4],
    int tid, int warp, int lane)
{
    // ---- layer 1 (4 -> 128, gated). Warp pair (q=warp>>1) sweeps points p=4i+q;
    //      each thread computes 2 channels and stores one bf16x2 word. ----
    {
        const int q = warp >> 1;
        const float bh0t = W.bh0 + W.wh0[3] * t;
        const float bg0t = W.bg0 + W.wg0[3] * t;
        const float bh1t = W.bh1 + W.wh1[3] * t;
        const float bg1t = W.bg1 + W.wg1[3] * t;
        #pragma unroll 4
        for (int i = 0; i < 32; ++i) {
            const int p = 4 * i + q;
            const float4 Y = *(const float4*)(yb + 4 * p);   // broadcast LDS.128
            float h0 = fmaf(W.wh0[0], Y.x, fmaf(W.wh0[1], Y.y, fmaf(W.wh0[2], Y.z, bh0t)));
            float g0 = fmaf(W.wg0[0], Y.x, fmaf(W.wg0[1], Y.y, fmaf(W.wg0[2], Y.z, bg0t)));
            float h1 = fmaf(W.wh1[0], Y.x, fmaf(W.wh1[1], Y.y, fmaf(W.wh1[2], Y.z, bh1t)));
            float g1 = fmaf(W.wg1[0], Y.x, fmaf(W.wg1[1], Y.y, fmaf(W.wg1[2], Y.z, bg1t)));
            float z0 = fmaxf(h0 * fsig(g0), 0.0f);
            float z1 = fmaxf(h1 * fsig(g1), 0.0f);
            *(uint32_t*)(z1wr + p * 64) = pack_bf2(z0, z1);
        }
    }
    __syncthreads();

    // ---- layer 2: two 128x128x128 bf16 GEMMs; gate-combine in regs;
    //      fused out-layer partials via 2-step shfl reduce -> Wpart. ----
    {
        const int g = lane >> 2, tg = lane & 3;
        const int row = warp * 16 + g;
        const float bh0 = B.h2b[row], bh1 = B.h2b[row + 8];
        const float bg0 = B.g2b[row], bg1 = B.g2b[row + 8];
        float* wpw = B.WP + warp * WP_WSTRIDE;

        #pragma unroll 2
        for (int n0 = 0; n0 < 128; n0 += 8) {
            const char* rowp = B.Z1 + (n0 + g) * 64 + tg * 16;
            uint4 f0 = *(const uint4*)(rowp);
            uint4 f1 = *(const uint4*)(rowp + PLANE_BYTES);
            uint4 f2 = *(const uint4*)(rowp + 2 * PLANE_BYTES);
            uint4 f3 = *(const uint4*)(rowp + 3 * PLANE_BYTES);
            float dh[4] = {0.f, 0.f, 0.f, 0.f};
            float dg[4] = {0.f, 0.f, 0.f, 0.f};
            mma16(dh, Ah[0], f0.x, f0.y);  mma16(dg, Ag[0], f0.x, f0.y);
            mma16(dh, Ah[1], f0.z, f0.w);  mma16(dg, Ag[1], f0.z, f0.w);
            mma16(dh, Ah[2], f1.x, f1.y);  mma16(dg, Ag[2], f1.x, f1.y);
            mma16(dh, Ah[3], f1.z, f1.w);  mma16(dg, Ag[3], f1.z, f1.w);
            mma16(dh, Ah[4], f2.x, f2.y);  mma16(dg, Ag[4], f2.x, f2.y);
            mma16(dh, Ah[5], f2.z, f2.w);  mma16(dg, Ag[5], f2.z, f2.w);
            mma16(dh, Ah[6], f3.x, f3.y);  mma16(dg, Ag[6], f3.x, f3.y);
            mma16(dh, Ah[7], f3.z, f3.w);  mma16(dg, Ag[7], f3.z, f3.w);

            float z00 = fmaxf((dh[0] + bh0) * fsig(dg[0] + bg0), 0.f);
            float z01 = fmaxf((dh[1] + bh0) * fsig(dg[1] + bg0), 0.f);
            float z10 = fmaxf((dh[2] + bh1) * fsig(dg[2] + bg1), 0.f);
            float z11 = fmaxf((dh[3] + bh1) * fsig(dg[3] + bg1), 0.f);

            float s0a = fmaf(O.o0a, z00, O.o0b * z10);
            float s0b = fmaf(O.o0a, z01, O.o0b * z11);
            float s1a = fmaf(O.o1a, z00, O.o1b * z10);
            float s1b = fmaf(O.o1a, z01, O.o1b * z11);
            float s2a = fmaf(O.o2a, z00, O.o2b * z10);
            float s2b = fmaf(O.o2a, z01, O.o2b * z11);
            #pragma unroll
            for (int m = 4; m <= 8; m <<= 1) {
                s0a += __shfl_xor_sync(0xffffffffu, s0a, m);
                s0b += __shfl_xor_sync(0xffffffffu, s0b, m);
                s1a += __shfl_xor_sync(0xffffffffu, s1a, m);
                s1b += __shfl_xor_sync(0xffffffffu, s1b, m);
                s2a += __shfl_xor_sync(0xffffffffu, s2a, m);
                s2b += __shfl_xor_sync(0xffffffffu, s2b, m);
            }
            const int out = g & 3, half = g >> 2;
            if (out < 3) {
                float sa = (out == 0) ? s0a : ((out == 1) ? s1a : s2a);
                float sb = (out == 0) ? s0b : ((out == 1) ? s1b : s2b);
                *(float2*)(wpw + half * WP_HSTRIDE + out * WP_OSTRIDE + n0 + 2 * tg)
                    = make_float2(sa, sb);
            }
        }
    }
    __syncthreads();

    // ---- reduce 16 per-(warp,half) partials -> kdst (tanh * 0.5) ----
    for (int i = tid; i < 384; i += THREADS) {
        const int c = i >> 7, p = i & 127;
        float s = B.ob[c];
        const float* wp = B.WP + c * WP_OSTRIDE + p;
        #pragma unroll
        for (int w8 = 0; w8 < 8; ++w8) {
            s += wp[w8 * WP_WSTRIDE] + wp[w8 * WP_WSTRIDE + WP_HSTRIDE];
        }
        kdst[4 * p + c] = tanhf(s) * 0.5f;
    }
    __syncthreads();
}

__global__ void __launch_bounds__(THREADS, 2)
node_kernel(const float* __restrict__ x0,
            const float* __restrict__ h1_w, const float* __restrict__ h1_b,
            const float* __restrict__ g1_w, const float* __restrict__ g1_b,
            const float* __restrict__ h2_w, const float* __restrict__ h2_b,
            const float* __restrict__ g2_w, const float* __restrict__ g2_b,
            const float* __restrict__ out_w, const float* __restrict__ out_b,
            float* __restrict__ yout, int P)
{
    extern __shared__ float sm[];
    Bufs B;
    B.Z1  = (char*)sm;
    B.WP  = sm + Z1_FLOATS;
    float* y0b = B.WP + WP_FLOATS;
    float* yb  = y0b + YBUF;
    float* k1b = yb  + YBUF;
    float* k2b = k1b + YBUF;
    float* k3b = k2b + YBUF;
    B.h2b = k3b + YBUF;
    B.g2b = B.h2b + 128;
    B.ob  = B.g2b + 128;

    const int tid  = threadIdx.x;
    const int warp = tid >> 5;
    const int lane = tid & 31;

    // stage biases into shared
    for (int i = tid; i < 128; i += THREADS) { B.h2b[i] = h2_b[i]; B.g2b[i] = g2_b[i]; }
    if (tid < 3) B.ob[tid] = out_b[tid];

    // this thread's Z1 word + write pointer
    const int w   = ((warp & 1) << 5) | lane;     // word 0..63 (channels 2w, 2w+1)
    char* z1wr = B.Z1 + (w >> 4) * PLANE_BYTES
               + (w & 3) * 16 + ((w >> 3) & 1) * 8 + ((w >> 2) & 1) * 4;

    // layer-1 weights for channels 2w, 2w+1
    L1W W;
    {
        const int c0 = 2 * w, c1 = 2 * w + 1;
        #pragma unroll
        for (int j = 0; j < 4; ++j) {
            W.wh0[j] = h1_w[c0 * 4 + j];  W.wg0[j] = g1_w[c0 * 4 + j];
            W.wh1[j] = h1_w[c1 * 4 + j];  W.wg1[j] = g1_w[c1 * 4 + j];
        }
        W.bh0 = h1_b[c0]; W.bg0 = g1_b[c0];
        W.bh1 = h1_b[c1]; W.bg1 = g1_b[c1];
    }

    // out-layer weights for rows (row, row+8)
    OW O;
    {
        const int row = warp * 16 + (lane >> 2);
        O.o0a = out_w[row];        O.o0b = out_w[row + 8];
        O.o1a = out_w[128 + row];  O.o1b = out_w[128 + row + 8];
        O.o2a = out_w[256 + row];  O.o2b = out_w[256 + row + 8];
    }

    // A fragments (bf16, m16n8k16): K=128 -> 8 k-steps
    uint32_t Ah[8][4], Ag[8][4];
    {
        const int g = lane >> 2, tg = lane & 3;
        const int r0 = warp * 16 + g;
        #pragma unroll
        for (int s = 0; s < 8; ++s) {
            const int k0 = 16 * s + 2 * tg;
            Ah[s][0] = pack_bf2(h2_w[r0 * 128 + k0],           h2_w[r0 * 128 + k0 + 1]);
            Ah[s][1] = pack_bf2(h2_w[(r0 + 8) * 128 + k0],     h2_w[(r0 + 8) * 128 + k0 + 1]);
            Ah[s][2] = pack_bf2(h2_w[r0 * 128 + k0 + 8],       h2_w[r0 * 128 + k0 + 9]);
            Ah[s][3] = pack_bf2(h2_w[(r0 + 8) * 128 + k0 + 8], h2_w[(r0 + 8) * 128 + k0 + 9]);
            Ag[s][0] = pack_bf2(g2_w[r0 * 128 + k0],           g2_w[r0 * 128 + k0 + 1]);
            Ag[s][1] = pack_bf2(g2_w[(r0 + 8) * 128 + k0],     g2_w[(r0 + 8) * 128 + k0 + 1]);
            Ag[s][2] = pack_bf2(g2_w[r0 * 128 + k0 + 8],       g2_w[r0 * 128 + k0 + 9]);
            Ag[s][3] = pack_bf2(g2_w[(r0 + 8) * 128 + k0 + 8], g2_w[(r0 + 8) * 128 + k0 + 9]);
        }
    }

    // load y0 (x0) for this block's 128 points into [p][4] layout
    const int p0 = blockIdx.x * TILE;
    for (int i = tid; i < 4 * TILE; i += THREADS) {
        int pl = i >> 2, c = i & 3;
        int pg = p0 + pl;
        float v = 0.f;
        if (c < 3 && pg < P) {
            int b = pg / NPER, n = pg - b * NPER;
            v = x0[(b * 3 + c) * NPER + n];
        }
        y0b[i] = v; yb[i] = v;
    }
    __syncthreads();

    const float third = 1.0f / 3.0f;

    // RK4 3/8 rule
    field_eval(0.0f, yb, k1b, B, W, O, z1wr, Ah, Ag, tid, warp, lane);
    if (tid < 128) {
        float4 y0 = *(float4*)(y0b + 4 * tid);
        float4 a  = *(float4*)(k1b + 4 * tid);
        float4 r;
        r.x = y0.x + a.x * third; r.y = y0.y + a.y * third;
        r.z = y0.z + a.z * third; r.w = 0.f;
        *(float4*)(yb + 4 * tid) = r;
    }
    __syncthreads();

    field_eval(third, yb, k2b, B, W, O, z1wr, Ah, Ag, tid, warp, lane);
    if (tid < 128) {
        float4 y0 = *(float4*)(y0b + 4 * tid);
        float4 a  = *(float4*)(k1b + 4 * tid);
        float4 b2 = *(float4*)(k2b + 4 * tid);
        float4 r;
        r.x = y0.x + (b2.x - a.x * third); r.y = y0.y + (b2.y - a.y * third);
        r.z = y0.z + (b2.z - a.z * third); r.w = 0.f;
        *(float4*)(yb + 4 * tid) = r;
    }
    __syncthreads();

    field_eval(third * 2.0f, yb, k3b, B, W, O, z1wr, Ah, Ag, tid, warp, lane);
    if (tid < 128) {
        float4 y0 = *(float4*)(y0b + 4 * tid);
        float4 a  = *(float4*)(k1b + 4 * tid);
        float4 b2 = *(float4*)(k2b + 4 * tid);
        float4 c3 = *(float4*)(k3b + 4 * tid);
        float4 r, f;
        r.x = y0.x + (a.x - b2.x + c3.x); r.y = y0.y + (a.y - b2.y + c3.y);
        r.z = y0.z + (a.z - b2.z + c3.z); r.w = 0.f;
        f.x = a.x + 3.0f * (b2.x + c3.x); f.y = a.y + 3.0f * (b2.y + c3.y);
        f.z = a.z + 3.0f * (b2.z + c3.z); f.w = 0.f;
        *(float4*)(yb + 4 * tid)  = r;
        *(float4*)(k1b + 4 * tid) = f;   // fold k1 + 3*(k2+k3)
    }
    __syncthreads();

    field_eval(1.0f, yb, k2b, B, W, O, z1wr, Ah, Ag, tid, warp, lane);  // k4 -> k2b

    // out = y0 + (k1 + 3*(k2+k3) + k4) / 8
    for (int i = tid; i < 3 * TILE; i += THREADS) {
        int c = i >> 7, pl = i & 127;
        int pg = p0 + pl;
        if (pg < P) {
            int b = pg / NPER, n = pg - b * NPER;
            yout[(b * 3 + c) * NPER + n] =
                y0b[4 * pl + c] + (k1b[4 * pl + c] + k2b[4 * pl + c]) * 0.125f;
        }
    }
}

extern "C" void kernel_launch(void* const* d_in, const int* in_sizes, int n_in,
                              void* d_out, int out_size) {
    const float* x0    = (const float*)d_in[0];
    const float* h1_w  = (const float*)d_in[1];
    const float* h1_b  = (const float*)d_in[2];
    const float* g1_w  = (const float*)d_in[3];
    const float* g1_b  = (const float*)d_in[4];
    const float* h2_w  = (const float*)d_in[5];
    const float* h2_b  = (const float*)d_in[6];
    const float* g2_w  = (const float*)d_in[7];
    const float* g2_b  = (const float*)d_in[8];
    const float* out_w = (const float*)d_in[9];
    const float* out_b = (const float*)d_in[10];
    float* yout = (float*)d_out;

    const int P = in_sizes[0] / 3;                 // total points = B*N
    const int blocks = (P + TILE - 1) / TILE;      // 3125
    const size_t smem = SMEM_FLOATS * sizeof(float);

    cudaFuncSetAttribute(node_kernel, cudaFuncAttributeMaxDynamicSharedMemorySize, (int)smem);
    node_kernel<<<blocks, THREADS, smem>>>(x0, h1_w, h1_b, g1_w, g1_b,
                                           h2_w, h2_b, g2_w, g2_b,
                                           out_w, out_b, yout, P);
}

// round 11
// speedup vs baseline: 2.4550x; 1.0879x over previous
#include <cuda_runtime.h>
#include <cuda_bf16.h>
#include <stdint.h>

#define THREADS 256
#define TILE 128
#define NPER 50000

// Z1: 4 k-planes (each covers 2 k-steps = 32 channels). Plane holds 128 points x 64B.
#define PLANE_BYTES 8256
#define Z1_FLOATS (4 * PLANE_BYTES / 4)      // 8256 floats
// Wpart: [8 warps][2 g-halves][3 outs][128 pts (+pad)]
#define WP_OSTRIDE 136
#define WP_HSTRIDE (3 * WP_OSTRIDE)          // 408
#define WP_WSTRIDE (2 * WP_HSTRIDE)          // 816
#define WP_FLOATS  (8 * WP_WSTRIDE)          // 6528
#define YBUF 512                              // 128 points x float4

#define SMEM_FLOATS (Z1_FLOATS + WP_FLOATS + 4*YBUF + 256 + 4)

// Packed, fragment-ordered bf16 A-operands (g2 pre-scaled by 0.5).
// Layout: [thread(tid 0..255)][s 0..7] of uint4 (4 regs).
__device__ uint4 g_Ah[256 * 8];
__device__ uint4 g_Ag[256 * 8];

static __device__ __forceinline__ float tanha(float x) {
    float r;
    asm("tanh.approx.f32 %0, %1;" : "=f"(r) : "f"(x));
    return r;
}
// sigmoid from HALF-SCALED preactivation: sig(2x) where x is given
static __device__ __forceinline__ float fsig2(float x_half) {
    return fmaf(tanha(x_half), 0.5f, 0.5f);
}
static __device__ __forceinline__ uint32_t pack_bf2(float lo, float hi) {
    __nv_bfloat162 v = __floats2bfloat162_rn(lo, hi);
    return *(uint32_t*)&v;
}
static __device__ __forceinline__ void mma16(float d[4], const uint32_t a[4],
                                             uint32_t b0, uint32_t b1) {
    asm volatile(
        "mma.sync.aligned.m16n8k16.row.col.f32.bf16.bf16.f32 "
        "{%0,%1,%2,%3}, {%4,%5,%6,%7}, {%8,%9}, {%0,%1,%2,%3};\n"
        : "+f"(d[0]), "+f"(d[1]), "+f"(d[2]), "+f"(d[3])
        : "r"(a[0]), "r"(a[1]), "r"(a[2]), "r"(a[3]), "r"(b0), "r"(b1));
}

// ---- prep kernel: pack A fragments into g_Ah / g_Ag ----
__global__ void prep_kernel(const float* __restrict__ h2w,
                            const float* __restrict__ g2w) {
    int idx = blockIdx.x * blockDim.x + threadIdx.x;   // 0..4095
    if (idx >= 4096) return;
    int s    = idx & 7;
    int wl   = (idx >> 3) & 255;
    int gemm = idx >> 11;
    int warp = wl >> 5, lane = wl & 31;
    int g = lane >> 2, tg = lane & 3;
    int r0 = warp * 16 + g, k0 = 16 * s + 2 * tg;
    const float* w = gemm ? g2w : h2w;
    float sc = gemm ? 0.5f : 1.0f;
    uint4 v;
    v.x = pack_bf2(sc * w[r0 * 128 + k0],           sc * w[r0 * 128 + k0 + 1]);
    v.y = pack_bf2(sc * w[(r0 + 8) * 128 + k0],     sc * w[(r0 + 8) * 128 + k0 + 1]);
    v.z = pack_bf2(sc * w[r0 * 128 + k0 + 8],       sc * w[r0 * 128 + k0 + 9]);
    v.w = pack_bf2(sc * w[(r0 + 8) * 128 + k0 + 8], sc * w[(r0 + 8) * 128 + k0 + 9]);
    (gemm ? g_Ag : g_Ah)[wl * 8 + s] = v;
}

struct Bufs {
    char  *Z1;
    float *WP, *h2b, *g2b, *ob;
};
struct L1W {
    float wh0[4], wg0[4], bh0, bg0;   // wg/bg pre-scaled by 0.5
    float wh1[4], wg1[4], bh1, bg1;
};
struct OW {
    float o0a, o0b, o1a, o1b, o2a, o2b;
};

// One field evaluation; STAGE selects fused RK update in the reduce phase.
template <int STAGE>
static __device__ __forceinline__ void field_eval(
    float t, float* __restrict__ yb,
    float* __restrict__ y0b, float* __restrict__ k1b, float* __restrict__ k2b,
    const Bufs& B, const L1W& W, const OW& O, char* __restrict__ z1wr,
    const uint32_t (&Ah)[8][4], const uint32_t (&Ag)[8][4],
    int tid, int warp, int lane, int p0, float* __restrict__ yout, int P)
{
    // ---- layer 1 (4 -> 128, gated) ----
    {
        const int q = warp >> 1;
        const float bh0t = W.bh0 + W.wh0[3] * t;
        const float bg0t = W.bg0 + W.wg0[3] * t;   // half-scaled
        const float bh1t = W.bh1 + W.wh1[3] * t;
        const float bg1t = W.bg1 + W.wg1[3] * t;   // half-scaled
        #pragma unroll 4
        for (int i = 0; i < 32; ++i) {
            const int p = 4 * i + q;
            const float4 Y = *(const float4*)(yb + 4 * p);   // broadcast LDS.128
            float h0 = fmaf(W.wh0[0], Y.x, fmaf(W.wh0[1], Y.y, fmaf(W.wh0[2], Y.z, bh0t)));
            float g0 = fmaf(W.wg0[0], Y.x, fmaf(W.wg0[1], Y.y, fmaf(W.wg0[2], Y.z, bg0t)));
            float h1 = fmaf(W.wh1[0], Y.x, fmaf(W.wh1[1], Y.y, fmaf(W.wh1[2], Y.z, bh1t)));
            float g1 = fmaf(W.wg1[0], Y.x, fmaf(W.wg1[1], Y.y, fmaf(W.wg1[2], Y.z, bg1t)));
            float z0 = fmaxf(h0 * fsig2(g0), 0.0f);
            float z1 = fmaxf(h1 * fsig2(g1), 0.0f);
            *(uint32_t*)(z1wr + p * 64) = pack_bf2(z0, z1);
        }
    }
    __syncthreads();

    // ---- layer 2: two bf16 GEMMs; bias in accumulator init; fused out partials ----
    {
        const int g = lane >> 2, tg = lane & 3;
        const int row = warp * 16 + g;
        const float bh0 = B.h2b[row], bh1 = B.h2b[row + 8];
        const float bg0 = B.g2b[row], bg1 = B.g2b[row + 8];   // pre-scaled 0.5
        float* wpw = B.WP + warp * WP_WSTRIDE;

        #pragma unroll 2
        for (int n0 = 0; n0 < 128; n0 += 8) {
            const char* rowp = B.Z1 + (n0 + g) * 64 + tg * 16;
            uint4 f0 = *(const uint4*)(rowp);
            uint4 f1 = *(const uint4*)(rowp + PLANE_BYTES);
            uint4 f2 = *(const uint4*)(rowp + 2 * PLANE_BYTES);
            uint4 f3 = *(const uint4*)(rowp + 3 * PLANE_BYTES);
            float dh[4] = {bh0, bh0, bh1, bh1};
            float dg[4] = {bg0, bg0, bg1, bg1};
            mma16(dh, Ah[0], f0.x, f0.y);  mma16(dg, Ag[0], f0.x, f0.y);
            mma16(dh, Ah[1], f0.z, f0.w);  mma16(dg, Ag[1], f0.z, f0.w);
            mma16(dh, Ah[2], f1.x, f1.y);  mma16(dg, Ag[2], f1.x, f1.y);
            mma16(dh, Ah[3], f1.z, f1.w);  mma16(dg, Ag[3], f1.z, f1.w);
            mma16(dh, Ah[4], f2.x, f2.y);  mma16(dg, Ag[4], f2.x, f2.y);
            mma16(dh, Ah[5], f2.z, f2.w);  mma16(dg, Ag[5], f2.z, f2.w);
            mma16(dh, Ah[6], f3.x, f3.y);  mma16(dg, Ag[6], f3.x, f3.y);
            mma16(dh, Ah[7], f3.z, f3.w);  mma16(dg, Ag[7], f3.z, f3.w);

            float z00 = fmaxf(dh[0] * fsig2(dg[0]), 0.f);
            float z01 = fmaxf(dh[1] * fsig2(dg[1]), 0.f);
            float z10 = fmaxf(dh[2] * fsig2(dg[2]), 0.f);
            float z11 = fmaxf(dh[3] * fsig2(dg[3]), 0.f);

            float s0a = fmaf(O.o0a, z00, O.o0b * z10);
            float s0b = fmaf(O.o0a, z01, O.o0b * z11);
            float s1a = fmaf(O.o1a, z00, O.o1b * z10);
            float s1b = fmaf(O.o1a, z01, O.o1b * z11);
            float s2a = fmaf(O.o2a, z00, O.o2b * z10);
            float s2b = fmaf(O.o2a, z01, O.o2b * z11);
            #pragma unroll
            for (int m = 4; m <= 8; m <<= 1) {
                s0a += __shfl_xor_sync(0xffffffffu, s0a, m);
                s0b += __shfl_xor_sync(0xffffffffu, s0b, m);
                s1a += __shfl_xor_sync(0xffffffffu, s1a, m);
                s1b += __shfl_xor_sync(0xffffffffu, s1b, m);
                s2a += __shfl_xor_sync(0xffffffffu, s2a, m);
                s2b += __shfl_xor_sync(0xffffffffu, s2b, m);
            }
            const int out = g & 3, half = g >> 2;
            if (out < 3) {
                float sa = (out == 0) ? s0a : ((out == 1) ? s1a : s2a);
                float sb = (out == 0) ? s0b : ((out == 1) ? s1b : s2b);
                *(float2*)(wpw + half * WP_HSTRIDE + out * WP_OSTRIDE + n0 + 2 * tg)
                    = make_float2(sa, sb);
            }
        }
    }
    __syncthreads();

    // ---- reduce partials -> k, fused RK update ----
    const float third = 1.0f / 3.0f;
    for (int i = tid; i < 384; i += THREADS) {
        const int c = i >> 7, p = i & 127;
        float s = B.ob[c];
        const float* wp = B.WP + c * WP_OSTRIDE + p;
        #pragma unroll
        for (int w8 = 0; w8 < 8; ++w8)
            s += wp[w8 * WP_WSTRIDE] + wp[w8 * WP_WSTRIDE + WP_HSTRIDE];
        float k = tanhf(s) * 0.5f;
        const int j = 4 * p + c;
        if (STAGE == 0) {
            k1b[j] = k;
            yb[j]  = y0b[j] + k * third;
        } else if (STAGE == 1) {
            float a = k1b[j];
            k2b[j] = k;
            yb[j]  = y0b[j] + (k - a * third);
        } else if (STAGE == 2) {
            float a = k1b[j], b2 = k2b[j];
            yb[j]  = y0b[j] + (a - b2 + k);
            k1b[j] = a + 3.0f * (b2 + k);   // fold k1 + 3*(k2+k3)
        } else {
            int pg = p0 + p;
            if (pg < P) {
                int b = pg / NPER, n = pg - b * NPER;
                yout[(b * 3 + c) * NPER + n] = y0b[j] + (k1b[j] + k) * 0.125f;
            }
        }
    }
    if (STAGE < 3) __syncthreads();
}

__global__ void __launch_bounds__(THREADS, 2)
node_kernel(const float* __restrict__ x0,
            const float* __restrict__ h1_w, const float* __restrict__ h1_b,
            const float* __restrict__ g1_w, const float* __restrict__ g1_b,
            const float* __restrict__ h2_b_, const float* __restrict__ g2_b_,
            const float* __restrict__ out_w, const float* __restrict__ out_b,
            float* __restrict__ yout, int P)
{
    extern __shared__ float sm[];
    Bufs B;
    B.Z1  = (char*)sm;
    B.WP  = sm + Z1_FLOATS;
    float* y0b = B.WP + WP_FLOATS;
    float* yb  = y0b + YBUF;
    float* k1b = yb  + YBUF;
    float* k2b = k1b + YBUF;
    B.h2b = k2b + YBUF;
    B.g2b = B.h2b + 128;
    B.ob  = B.g2b + 128;

    const int tid  = threadIdx.x;
    const int warp = tid >> 5;
    const int lane = tid & 31;

    // stage biases into shared (g2 bias pre-scaled by 0.5)
    for (int i = tid; i < 128; i += THREADS) {
        B.h2b[i] = h2_b_[i];
        B.g2b[i] = 0.5f * g2_b_[i];
    }
    if (tid < 3) B.ob[tid] = out_b[tid];

    // this thread's Z1 word + write pointer
    const int w = ((warp & 1) << 5) | lane;     // word 0..63 (channels 2w, 2w+1)
    char* z1wr = B.Z1 + (w >> 4) * PLANE_BYTES
               + (w & 3) * 16 + ((w >> 3) & 1) * 8 + ((w >> 2) & 1) * 4;

    // layer-1 weights (gate path pre-scaled by 0.5)
    L1W W;
    {
        const int c0 = 2 * w, c1 = 2 * w + 1;
        #pragma unroll
        for (int j = 0; j < 4; ++j) {
            W.wh0[j] = h1_w[c0 * 4 + j];  W.wg0[j] = 0.5f * g1_w[c0 * 4 + j];
            W.wh1[j] = h1_w[c1 * 4 + j];  W.wg1[j] = 0.5f * g1_w[c1 * 4 + j];
        }
        W.bh0 = h1_b[c0]; W.bg0 = 0.5f * g1_b[c0];
        W.bh1 = h1_b[c1]; W.bg1 = 0.5f * g1_b[c1];
    }

    // out-layer weights for rows (row, row+8)
    OW O;
    {
        const int row = warp * 16 + (lane >> 2);
        O.o0a = out_w[row];        O.o0b = out_w[row + 8];
        O.o1a = out_w[128 + row];  O.o1b = out_w[128 + row + 8];
        O.o2a = out_w[256 + row];  O.o2b = out_w[256 + row + 8];
    }

    // A fragments: vector loads from prep-packed buffers
    uint32_t Ah[8][4], Ag[8][4];
    {
        const uint4* ph = g_Ah + tid * 8;
        const uint4* pg = g_Ag + tid * 8;
        #pragma unroll
        for (int s = 0; s < 8; ++s) {
            uint4 vh = ph[s], vg = pg[s];
            Ah[s][0] = vh.x; Ah[s][1] = vh.y; Ah[s][2] = vh.z; Ah[s][3] = vh.w;
            Ag[s][0] = vg.x; Ag[s][1] = vg.y; Ag[s][2] = vg.z; Ag[s][3] = vg.w;
        }
    }

    // load y0 (x0) for this block's 128 points into [p][4] layout
    const int p0 = blockIdx.x * TILE;
    for (int i = tid; i < 4 * TILE; i += THREADS) {
        int pl = i >> 2, c = i & 3;
        int pg = p0 + pl;
        float v = 0.f;
        if (c < 3 && pg < P) {
            int b = pg / NPER, n = pg - b * NPER;
            v = x0[(b * 3 + c) * NPER + n];
        }
        y0b[i] = v; yb[i] = v;
    }
    __syncthreads();

    const float third = 1.0f / 3.0f;

    // RK4 3/8 rule (RK updates fused into each field_eval's reduce phase)
    field_eval<0>(0.0f,          yb, y0b, k1b, k2b, B, W, O, z1wr, Ah, Ag,
                  tid, warp, lane, p0, yout, P);
    field_eval<1>(third,         yb, y0b, k1b, k2b, B, W, O, z1wr, Ah, Ag,
                  tid, warp, lane, p0, yout, P);
    field_eval<2>(third * 2.0f,  yb, y0b, k1b, k2b, B, W, O, z1wr, Ah, Ag,
                  tid, warp, lane, p0, yout, P);
    field_eval<3>(1.0f,          yb, y0b, k1b, k2b, B, W, O, z1wr, Ah, Ag,
                  tid, warp, lane, p0, yout, P);
}

extern "C" void kernel_launch(void* const* d_in, const int* in_sizes, int n_in,
                              void* d_out, int out_size) {
    const float* x0    = (const float*)d_in[0];
    const float* h1_w  = (const float*)d_in[1];
    const float* h1_b  = (const float*)d_in[2];
    const float* g1_w  = (const float*)d_in[3];
    const float* g1_b  = (const float*)d_in[4];
    const float* h2_w  = (const float*)d_in[5];
    const float* h2_b  = (const float*)d_in[6];
    const float* g2_w  = (const float*)d_in[7];
    const float* g2_b  = (const float*)d_in[8];
    const float* out_w = (const float*)d_in[9];
    const float* out_b = (const float*)d_in[10];
    float* yout = (float*)d_out;

    const int P = in_sizes[0] / 3;                 // total points = B*N
    const int blocks = (P + TILE - 1) / TILE;      // 3125
    const size_t smem = SMEM_FLOATS * sizeof(float);

    prep_kernel<<<8, 512>>>(h2_w, g2_w);

    cudaFuncSetAttribute(node_kernel, cudaFuncAttributeMaxDynamicSharedMemorySize, (int)smem);
    node_kernel<<<blocks, THREADS, smem>>>(x0, h1_w, h1_b, g1_w, g1_b,
                                           h2_b, g2_b,
                                           out_w, out_b, yout, P);
}

// round 12
// speedup vs baseline: 2.7600x; 1.1243x over previous
#include <cuda_runtime.h>
#include <cuda_bf16.h>
#include <stdint.h>

#define THREADS 256
#define TILE 128
#define NPER 50000

// Z1/Z2: 4 k-planes (each covers 2 k-steps = 32 channels). Plane = 128 points x 64B (+64 pad).
#define PLANE_BYTES 8256
#define ZBUF_FLOATS (4 * PLANE_BYTES / 4)    // 8256 floats each
#define YBUF 512                              // 128 points x float4

// smem floats: Z1 + Z2 + y0/y/k1/k2 + h2b/g2b
#define SMEM_FLOATS (2 * ZBUF_FLOATS + 4 * YBUF + 256)

// Packed, fragment-ordered bf16 A-operands (g2 pre-scaled by 0.5).
__device__ uint4 g_Ah[256 * 8];
__device__ uint4 g_Ag[256 * 8];
// Out-layer A fragments (warp-invariant): [lane 0..31][s 0..7] = (a0, a2)
__device__ uint2 g_Ao[32 * 8];

static __device__ __forceinline__ float tanha(float x) {
    float r;
    asm("tanh.approx.f32 %0, %1;" : "=f"(r) : "f"(x));
    return r;
}
// sigmoid from HALF-SCALED preactivation
static __device__ __forceinline__ float fsig2(float x_half) {
    return fmaf(tanha(x_half), 0.5f, 0.5f);
}
static __device__ __forceinline__ uint32_t pack_bf2(float lo, float hi) {
    __nv_bfloat162 v = __floats2bfloat162_rn(lo, hi);
    return *(uint32_t*)&v;
}
static __device__ __forceinline__ void mma16(float d[4], const uint32_t a[4],
                                             uint32_t b0, uint32_t b1) {
    asm volatile(
        "mma.sync.aligned.m16n8k16.row.col.f32.bf16.bf16.f32 "
        "{%0,%1,%2,%3}, {%4,%5,%6,%7}, {%8,%9}, {%0,%1,%2,%3};\n"
        : "+f"(d[0]), "+f"(d[1]), "+f"(d[2]), "+f"(d[3])
        : "r"(a[0]), "r"(a[1]), "r"(a[2]), "r"(a[3]), "r"(b0), "r"(b1));
}
// out-GEMM mma: a1 = a3 = 0 (rows 8..15 of OW are zero)
static __device__ __forceinline__ void mma16o(float d[4], uint32_t a0, uint32_t a2,
                                              uint32_t b0, uint32_t b1) {
    asm volatile(
        "mma.sync.aligned.m16n8k16.row.col.f32.bf16.bf16.f32 "
        "{%0,%1,%2,%3}, {%4,%5,%6,%7}, {%8,%9}, {%0,%1,%2,%3};\n"
        : "+f"(d[0]), "+f"(d[1]), "+f"(d[2]), "+f"(d[3])
        : "r"(a0), "r"(0u), "r"(a2), "r"(0u), "r"(b0), "r"(b1));
}

// ---- prep kernel: pack A fragments (h2, g2 scaled, out_w) ----
__global__ void prep_kernel(const float* __restrict__ h2w,
                            const float* __restrict__ g2w,
                            const float* __restrict__ outw) {
    int idx = blockIdx.x * blockDim.x + threadIdx.x;
    if (idx < 4096) {
        int s    = idx & 7;
        int wl   = (idx >> 3) & 255;
        int gemm = idx >> 11;
        int warp = wl >> 5, lane = wl & 31;
        int g = lane >> 2, tg = lane & 3;
        int r0 = warp * 16 + g, k0 = 16 * s + 2 * tg;
        const float* w = gemm ? g2w : h2w;
        float sc = gemm ? 0.5f : 1.0f;
        uint4 v;
        v.x = pack_bf2(sc * w[r0 * 128 + k0],           sc * w[r0 * 128 + k0 + 1]);
        v.y = pack_bf2(sc * w[(r0 + 8) * 128 + k0],     sc * w[(r0 + 8) * 128 + k0 + 1]);
        v.z = pack_bf2(sc * w[r0 * 128 + k0 + 8],       sc * w[r0 * 128 + k0 + 9]);
        v.w = pack_bf2(sc * w[(r0 + 8) * 128 + k0 + 8], sc * w[(r0 + 8) * 128 + k0 + 9]);
        (gemm ? g_Ag : g_Ah)[wl * 8 + s] = v;
    } else if (idx < 4096 + 256) {
        int i2 = idx - 4096;
        int s = i2 & 7, lane = i2 >> 3;
        int g = lane >> 2, tg = lane & 3;
        int k0 = 16 * s + 2 * tg;
        uint2 v = make_uint2(0u, 0u);
        if (g < 3) {
            v.x = pack_bf2(outw[g * 128 + k0],     outw[g * 128 + k0 + 1]);
            v.y = pack_bf2(outw[g * 128 + k0 + 8], outw[g * 128 + k0 + 9]);
        }
        g_Ao[lane * 8 + s] = v;
    }
}

struct Bufs {
    char  *Z1, *Z2;
    float *h2b, *g2b;
};
struct L1W {
    float wh0[4], wg0[4], bh0, bg0;   // wg/bg pre-scaled by 0.5
    float wh1[4], wg1[4], bh1, bg1;
};

// One field evaluation; STAGE selects fused RK update in the out-GEMM epilogue.
template <int STAGE>
static __device__ __forceinline__ void field_eval(
    float t, float* __restrict__ yb,
    float* __restrict__ y0b, float* __restrict__ k1b, float* __restrict__ k2b,
    const Bufs& B, const L1W& W, char* __restrict__ z1wr, char* __restrict__ z2wr,
    const uint32_t (&Ah)[8][4], const uint32_t (&Ag)[8][4], float obg,
    int tid, int warp, int lane, int p0, float* __restrict__ yout, int P)
{
    const int g = lane >> 2, tg = lane & 3;

    // ---- layer 1 (4 -> 128, gated) ----
    {
        const int q = warp >> 1;
        const float bh0t = W.bh0 + W.wh0[3] * t;
        const float bg0t = W.bg0 + W.wg0[3] * t;
        const float bh1t = W.bh1 + W.wh1[3] * t;
        const float bg1t = W.bg1 + W.wg1[3] * t;
        #pragma unroll 4
        for (int i = 0; i < 32; ++i) {
            const int p = 4 * i + q;
            const float4 Y = *(const float4*)(yb + 4 * p);   // broadcast LDS.128
            float h0 = fmaf(W.wh0[0], Y.x, fmaf(W.wh0[1], Y.y, fmaf(W.wh0[2], Y.z, bh0t)));
            float g0 = fmaf(W.wg0[0], Y.x, fmaf(W.wg0[1], Y.y, fmaf(W.wg0[2], Y.z, bg0t)));
            float h1 = fmaf(W.wh1[0], Y.x, fmaf(W.wh1[1], Y.y, fmaf(W.wh1[2], Y.z, bh1t)));
            float g1 = fmaf(W.wg1[0], Y.x, fmaf(W.wg1[1], Y.y, fmaf(W.wg1[2], Y.z, bg1t)));
            float z0 = fmaxf(h0 * fsig2(g0), 0.0f);
            float z1 = fmaxf(h1 * fsig2(g1), 0.0f);
            *(uint32_t*)(z1wr + p * 64) = pack_bf2(z0, z1);
        }
    }
    __syncthreads();

    // ---- layer 2: two bf16 GEMMs; gate-combine in regs; z2 -> Z2 (B-fragment layout) ----
    {
        const int row = warp * 16 + g;
        const float bh0 = B.h2b[row], bh1 = B.h2b[row + 8];
        const float bg0 = B.g2b[row], bg1 = B.g2b[row + 8];
        const bool evn = ((lane & 4) == 0);

        #pragma unroll 2
        for (int n0 = 0; n0 < 128; n0 += 8) {
            const char* rowp = B.Z1 + (n0 + g) * 64 + tg * 16;
            uint4 f0 = *(const uint4*)(rowp);
            uint4 f1 = *(const uint4*)(rowp + PLANE_BYTES);
            uint4 f2 = *(const uint4*)(rowp + 2 * PLANE_BYTES);
            uint4 f3 = *(const uint4*)(rowp + 3 * PLANE_BYTES);
            float dh[4] = {bh0, bh0, bh1, bh1};
            float dg[4] = {bg0, bg0, bg1, bg1};
            mma16(dh, Ah[0], f0.x, f0.y);  mma16(dg, Ag[0], f0.x, f0.y);
            mma16(dh, Ah[1], f0.z, f0.w);  mma16(dg, Ag[1], f0.z, f0.w);
            mma16(dh, Ah[2], f1.x, f1.y);  mma16(dg, Ag[2], f1.x, f1.y);
            mma16(dh, Ah[3], f1.z, f1.w);  mma16(dg, Ag[3], f1.z, f1.w);
            mma16(dh, Ah[4], f2.x, f2.y);  mma16(dg, Ag[4], f2.x, f2.y);
            mma16(dh, Ah[5], f2.z, f2.w);  mma16(dg, Ag[5], f2.z, f2.w);
            mma16(dh, Ah[6], f3.x, f3.y);  mma16(dg, Ag[6], f3.x, f3.y);
            mma16(dh, Ah[7], f3.z, f3.w);  mma16(dg, Ag[7], f3.z, f3.w);

            float z00 = fmaxf(dh[0] * fsig2(dg[0]), 0.f);
            float z01 = fmaxf(dh[1] * fsig2(dg[1]), 0.f);
            float z10 = fmaxf(dh[2] * fsig2(dg[2]), 0.f);
            float z11 = fmaxf(dh[3] * fsig2(dg[3]), 0.f);

            // pair adjacent channels (g <-> g^1) and store z2 in B-fragment layout
            float rz00 = __shfl_xor_sync(0xffffffffu, z00, 4);
            float rz01 = __shfl_xor_sync(0xffffffffu, z01, 4);
            float rz10 = __shfl_xor_sync(0xffffffffu, z10, 4);
            float rz11 = __shfl_xor_sync(0xffffffffu, z11, 4);
            float loA = evn ? z00 : rz01,  hiA = evn ? rz00 : z01;
            float loB = evn ? z10 : rz11,  hiB = evn ? rz10 : z11;
            int   c   = n0 + 2 * tg + (evn ? 0 : 1);
            *(uint2*)(z2wr + c * 64) = make_uint2(pack_bf2(loA, hiA), pack_bf2(loB, hiB));
        }
    }

    // prefetch out-layer A fragments (latency hidden by the barrier)
    uint2 ao[8];
    {
        const uint2* p = g_Ao + lane * 8;
        #pragma unroll
        for (int s = 0; s < 8; ++s) ao[s] = p[s];
    }
    __syncthreads();

    // ---- out-GEMM: D[16(3 used) x 16 pts per warp] = OW x Z2, fused tanh + RK ----
    const float third = 1.0f / 3.0f;
    #pragma unroll
    for (int tile = 0; tile < 2; ++tile) {
        const int nc = warp * 16 + tile * 8;
        const char* rowp = B.Z2 + (nc + g) * 64 + tg * 16;
        uint4 f0 = *(const uint4*)(rowp);
        uint4 f1 = *(const uint4*)(rowp + PLANE_BYTES);
        uint4 f2 = *(const uint4*)(rowp + 2 * PLANE_BYTES);
        uint4 f3 = *(const uint4*)(rowp + 3 * PLANE_BYTES);
        float d[4] = {0.f, 0.f, 0.f, 0.f};
        mma16o(d, ao[0].x, ao[0].y, f0.x, f0.y);
        mma16o(d, ao[1].x, ao[1].y, f0.z, f0.w);
        mma16o(d, ao[2].x, ao[2].y, f1.x, f1.y);
        mma16o(d, ao[3].x, ao[3].y, f1.z, f1.w);
        mma16o(d, ao[4].x, ao[4].y, f2.x, f2.y);
        mma16o(d, ao[5].x, ao[5].y, f2.z, f2.w);
        mma16o(d, ao[6].x, ao[6].y, f3.x, f3.y);
        mma16o(d, ao[7].x, ao[7].y, f3.z, f3.w);

        if (g < 3) {
            #pragma unroll
            for (int colh = 0; colh < 2; ++colh) {
                const int pl = nc + 2 * tg + colh;
                const int j  = 4 * pl + g;
                float k = tanha(d[colh] + obg) * 0.5f;
                if (STAGE == 0) {
                    k1b[j] = k;
                    yb[j]  = y0b[j] + k * third;
                } else if (STAGE == 1) {
                    float a = k1b[j];
                    k2b[j] = k;
                    yb[j]  = y0b[j] + (k - a * third);
                } else if (STAGE == 2) {
                    float a = k1b[j], b2 = k2b[j];
                    yb[j]  = y0b[j] + (a - b2 + k);
                    k1b[j] = a + 3.0f * (b2 + k);   // fold k1 + 3*(k2+k3)
                } else {
                    int pg = p0 + pl;
                    if (pg < P) {
                        int b = pg / NPER, n = pg - b * NPER;
                        yout[(b * 3 + g) * NPER + n] = y0b[j] + (k1b[j] + k) * 0.125f;
                    }
                }
            }
        }
    }
    if (STAGE < 3) __syncthreads();
}

__global__ void __launch_bounds__(THREADS, 2)
node_kernel(const float* __restrict__ x0,
            const float* __restrict__ h1_w, const float* __restrict__ h1_b,
            const float* __restrict__ g1_w, const float* __restrict__ g1_b,
            const float* __restrict__ h2_b_, const float* __restrict__ g2_b_,
            const float* __restrict__ out_b,
            float* __restrict__ yout, int P)
{
    extern __shared__ float sm[];
    Bufs B;
    B.Z1  = (char*)sm;
    B.Z2  = (char*)sm + 4 * PLANE_BYTES;
    float* y0b = sm + 2 * ZBUF_FLOATS;
    float* yb  = y0b + YBUF;
    float* k1b = yb  + YBUF;
    float* k2b = k1b + YBUF;
    B.h2b = k2b + YBUF;
    B.g2b = B.h2b + 128;

    const int tid  = threadIdx.x;
    const int warp = tid >> 5;
    const int lane = tid & 31;
    const int g    = lane >> 2;

    // stage biases into shared (g2 bias pre-scaled by 0.5)
    for (int i = tid; i < 128; i += THREADS) {
        B.h2b[i] = h2_b_[i];
        B.g2b[i] = 0.5f * g2_b_[i];
    }
    const float obg = (g < 3) ? out_b[g] : 0.0f;

    // this thread's Z1 write pointer (word = channels 2w, 2w+1)
    const int w = ((warp & 1) << 5) | lane;
    char* z1wr = B.Z1 + (w >> 4) * PLANE_BYTES
               + (w & 3) * 16 + ((w >> 3) & 1) * 8 + ((w >> 2) & 1) * 4;
    // Z2 write pointer for the L2 epilogue (add c*64 per store)
    char* z2wr = B.Z2 + (warp >> 1) * PLANE_BYTES + (g >> 1) * 16 + (warp & 1) * 8;

    // layer-1 weights (gate path pre-scaled by 0.5)
    L1W W;
    {
        const int c0 = 2 * w, c1 = 2 * w + 1;
        #pragma unroll
        for (int j = 0; j < 4; ++j) {
            W.wh0[j] = h1_w[c0 * 4 + j];  W.wg0[j] = 0.5f * g1_w[c0 * 4 + j];
            W.wh1[j] = h1_w[c1 * 4 + j];  W.wg1[j] = 0.5f * g1_w[c1 * 4 + j];
        }
        W.bh0 = h1_b[c0]; W.bg0 = 0.5f * g1_b[c0];
        W.bh1 = h1_b[c1]; W.bg1 = 0.5f * g1_b[c1];
    }

    // A fragments: vector loads from prep-packed buffers
    uint32_t Ah[8][4], Ag[8][4];
    {
        const uint4* ph = g_Ah + tid * 8;
        const uint4* pg = g_Ag + tid * 8;
        #pragma unroll
        for (int s = 0; s < 8; ++s) {
            uint4 vh = ph[s], vg = pg[s];
            Ah[s][0] = vh.x; Ah[s][1] = vh.y; Ah[s][2] = vh.z; Ah[s][3] = vh.w;
            Ag[s][0] = vg.x; Ag[s][1] = vg.y; Ag[s][2] = vg.z; Ag[s][3] = vg.w;
        }
    }

    // load y0 (x0) for this block's 128 points into [p][4] layout
    const int p0 = blockIdx.x * TILE;
    for (int i = tid; i < 4 * TILE; i += THREADS) {
        int pl = i >> 2, c = i & 3;
        int pg = p0 + pl;
        float v = 0.f;
        if (c < 3 && pg < P) {
            int b = pg / NPER, n = pg - b * NPER;
            v = x0[(b * 3 + c) * NPER + n];
        }
        y0b[i] = v; yb[i] = v;
    }
    __syncthreads();

    const float third = 1.0f / 3.0f;

    // RK4 3/8 rule (RK updates fused into the out-GEMM epilogue)
    field_eval<0>(0.0f,         yb, y0b, k1b, k2b, B, W, z1wr, z2wr, Ah, Ag, obg,
                  tid, warp, lane, p0, yout, P);
    field_eval<1>(third,        yb, y0b, k1b, k2b, B, W, z1wr, z2wr, Ah, Ag, obg,
                  tid, warp, lane, p0, yout, P);
    field_eval<2>(third * 2.0f, yb, y0b, k1b, k2b, B, W, z1wr, z2wr, Ah, Ag, obg,
                  tid, warp, lane, p0, yout, P);
    field_eval<3>(1.0f,         yb, y0b, k1b, k2b, B, W, z1wr, z2wr, Ah, Ag, obg,
                  tid, warp, lane, p0, yout, P);
}

extern "C" void kernel_launch(void* const* d_in, const int* in_sizes, int n_in,
                              void* d_out, int out_size) {
    const float* x0    = (const float*)d_in[0];
    const float* h1_w  = (const float*)d_in[1];
    const float* h1_b  = (const float*)d_in[2];
    const float* g1_w  = (const float*)d_in[3];
    const float* g1_b  = (const float*)d_in[4];
    const float* h2_w  = (const float*)d_in[5];
    const float* h2_b  = (const float*)d_in[6];
    const float* g2_w  = (const float*)d_in[7];
    const float* g2_b  = (const float*)d_in[8];
    const float* out_w = (const float*)d_in[9];
    const float* out_b = (const float*)d_in[10];
    float* yout = (float*)d_out;

    const int P = in_sizes[0] / 3;                 // total points = B*N
    const int blocks = (P + TILE - 1) / TILE;      // 3125
    const size_t smem = SMEM_FLOATS * sizeof(float);

    prep_kernel<<<9, 512>>>(h2_w, g2_w, out_w);

    cudaFuncSetAttribute(node_kernel, cudaFuncAttributeMaxDynamicSharedMemorySize, (int)smem);
    node_kernel<<<blocks, THREADS, smem>>>(x0, h1_w, h1_b, g1_w, g1_b,
                                           h2_b, g2_b, out_b, yout, P);
}